// round 6
// baseline (speedup 1.0000x reference)
#include <cuda_runtime.h>

#define N_ANCH 1000
#define N_FEAT 78
#define NT     256
#define LPC    2            // lanes (priors) per CTA
#define NCTA   512          // 64 images * 8 CTAs
#define K_MAX  64
#define FULL   0xffffffffu
#define SPSTR  80

__device__ float    g_part[1024 * 3];
__device__ unsigned g_ctr;

static __device__ __forceinline__ unsigned fkey(float f) {
    unsigned u = __float_as_uint(f);
    return (u & 0x80000000u) ? ~u : (u | 0x80000000u);
}
static __device__ __forceinline__ float wsum(float v) {
    #pragma unroll
    for (int o = 16; o; o >>= 1) v += __shfl_xor_sync(FULL, v, o);
    return v;
}
static __device__ __forceinline__ int wscan_incl(int v, int lane) {
    #pragma unroll
    for (int o = 1; o < 32; o <<= 1) {
        int t = __shfl_up_sync(FULL, v, o);
        if (lane >= o) v += t;
    }
    return v;
}

__global__ __launch_bounds__(NT, 4)
void lane_kernel(const float* __restrict__ output, const float* __restrict__ label,
                 float* __restrict__ out)
{
    __shared__ float A0[N_ANCH];
    __shared__ float A1[N_ANCH];
    __shared__ float c0s[N_ANCH];          // logits col0 -> focal f0
    __shared__ float c1s[N_ANCH];
    __shared__ float spsm[LPC * SPSTR];    // 2 priors
    __shared__ float wred[12 * 8];
    __shared__ int   iw[8];
    __shared__ int   hist[256];
    __shared__ int   sel[K_MAX];
    __shared__ int   si2[2];
    __shared__ float bres[12];
    __shared__ float bres2[4];
    __shared__ unsigned sAm;

    const int tid = threadIdx.x;
    const int wid = tid >> 5;
    const int l   = tid & 31;
    const int bx   = blockIdx.x;
    const int img  = bx >> 3;
    const int pair = bx & 7;               // priors {2*pair, 2*pair+1}
    const float* feat = output + (size_t)img * (N_ANCH * N_FEAT);

    for (int idx = tid; idx < LPC * N_FEAT; idx += NT) {
        int ll = idx / N_FEAT, j = idx - ll * N_FEAT;
        spsm[ll * SPSTR + j] = label[((size_t)img * 16 + pair * LPC + ll) * N_FEAT + j];
    }
    __syncthreads();

    // register-cached prior slices (per lane)
    const float spA0 = spsm[6 + l],           spA1 = spsm[38 + l];
    const float spB0 = spsm[SPSTR + 6 + l],   spB1 = spsm[SPSTR + 38 + l];
    const float spA2 = (l < 8) ? spsm[70 + l]          : 0.f;
    const float spB2 = (l < 8) ? spsm[SPSTR + 70 + l]  : 0.f;
    const float p0x = spsm[3], p0y = spsm[4], p0t = spsm[5];
    const float p1x = spsm[SPSTR + 3], p1y = spsm[SPSTR + 4], p1t = spsm[SPSTR + 5];

    float m0 = -3.4e38f, m1 = -3.4e38f;
    float a0 = 0.f, a1 = 0.f, a2 = 0.f, a3 = 0.f;
    float a4 = 0.f, a5 = 0.f, a6 = 0.f, a7 = 0.f;

    // ---------------- main pass: warp-cooperative, coalesced, no smem tile
    auto process = [&](int i) {
        const float* row = feat + i * N_FEAT;
        float h  = (l < 6) ? row[l] : 0.f;
        float va = row[6 + l];
        float vb = row[38 + l];
        float vc = (l < 8) ? row[70 + l] : 0.f;
        float pa = fabsf(va - spA0) + fabsf(vb - spA1) + fabsf(vc - spA2);
        float pb = fabsf(va - spB0) + fabsf(vb - spB1) + fabsf(vc - spB2);
        float La = wsum(pa);
        float Lb = wsum(pb);
        float v0 = __shfl_sync(FULL, h, 0), v1 = __shfl_sync(FULL, h, 1);
        float rx = __shfl_sync(FULL, h, 3), ry = __shfl_sync(FULL, h, 4);
        float rt = __shfl_sync(FULL, h, 5);
        m0 = fmaxf(m0, v0); m1 = fmaxf(m1, v1);
        // prior 0
        {
            float dx = rx - p0x, dy = ry - p0y, th = rt - p0t;
            float xy = sqrtf(dx * dx + dy * dy);
            float dis = La * (1.0f / 72.0f);
            float liou = 1.f - (2160.f - La) / (2160.f + La + 1e-9f);
            if (l == 0) { A0[i] = dis * xy * th; c0s[i] = v0; c1s[i] = v1; }
            a0 += xy * xy; a1 += th * th; a2 += dis * dis; a3 += liou;
        }
        // prior 1
        {
            float dx = rx - p1x, dy = ry - p1y, th = rt - p1t;
            float xy = sqrtf(dx * dx + dy * dy);
            float dis = Lb * (1.0f / 72.0f);
            float liou = 1.f - (2160.f - Lb) / (2160.f + Lb + 1e-9f);
            if (l == 1) A1[i] = dis * xy * th;
            a4 += xy * xy; a5 += th * th; a6 += dis * dis; a7 += liou;
        }
    };
    for (int t = 0; t < 62; ++t) {         // 62*2 + 1 = 125 anchors per warp
        process(wid + t * 16);
        process(wid + 8 + t * 16);
    }
    process(wid + 992);

    // ---------------- block-reduce: values identical across lanes -> lane0 only
    {
        if (l == 0) {
            wred[0 * 8 + wid] = m0;  wred[1 * 8 + wid] = m1;
            wred[2 * 8 + wid] = a0;  wred[3 * 8 + wid] = a1;
            wred[4 * 8 + wid] = a2;  wred[5 * 8 + wid] = a3;
            wred[6 * 8 + wid] = a4;  wred[7 * 8 + wid] = a5;
            wred[8 * 8 + wid] = a6;  wred[9 * 8 + wid] = a7;
        }
        __syncthreads();
        if (tid < 10) {
            float r = wred[tid * 8];
            if (tid < 2) { for (int w = 1; w < 8; ++w) r = fmaxf(r, wred[tid * 8 + w]); }
            else         { for (int w = 1; w < 8; ++w) r += wred[tid * 8 + w]; }
            bres[tid] = r;
        }
        __syncthreads();
    }
    const float M0 = bres[0], M1 = bres[1];

    // ---------------- softmax sums over smem logits
    float s0 = 0.f, s1 = 0.f;
    for (int i = tid; i < N_ANCH; i += NT) {
        s0 += expf(c0s[i] - M0);
        s1 += expf(c1s[i] - M1);
    }
    {
        float v;
        v = wsum(s0); if (l == 0) wred[0 * 8 + wid] = v;
        v = wsum(s1); if (l == 0) wred[1 * 8 + wid] = v;
        __syncthreads();
        if (tid < 2) {
            float r = 0.f;
            for (int w = 0; w < 8; ++w) r += wred[tid * 8 + w];
            bres[tid] = r;   // M0/M1 already in registers everywhere
        }
        __syncthreads();
    }
    const float lse0 = M0 + logf(bres[0]);
    const float lse1 = M1 + logf(bres[1]);

    // focal factors (feature-only), overwrite logit arrays
    for (int i = tid; i < N_ANCH; i += NT) {
        float ls0 = c0s[i] - lse0, e0 = expf(ls0);
        c0s[i] = (1.f - e0) * (1.f - e0) * ls0;
        float ls1 = c1s[i] - lse1, e1 = expf(ls1);
        c1s[i] = (1.f - e1) * (1.f - e1) * ls1;
    }
    __syncthreads();

    // ---------------- per-prior: cost finalize, radix-select, stage-2
    for (int l2 = 0; l2 < LPC; ++l2) {
        const float sxy   = bres[2 + l2 * 4 + 0];
        const float sth   = bres[2 + l2 * 4 + 1];
        const float sdis  = bres[2 + l2 * 4 + 2];
        const float sliou = bres[2 + l2 * 4 + 3];
        const float Nx  = fmaxf(sqrtf(sxy),  1e-12f);
        const float Nt2 = fmaxf(sqrtf(sth),  1e-12f);
        const float Nd  = fmaxf(sqrtf(sdis), 1e-12f);
        const float invn = 1.f / (Nx * Nt2 * Nd);
        int k = (int)sliou;
        if (k < 1) k = 1;
        if (k > K_MAX) k = K_MAX;
        const float* spl = spsm + l2 * SPSTR;
        const float p0 = spl[0], p1 = spl[1];
        float* A = l2 ? A1 : A0;

        for (int i = tid; i < N_ANCH; i += NT) {
            float tq = A[i] * invn;
            A[i] = 3.f * tq * tq + p0 * c0s[i] + p1 * c1s[i];
        }
        __syncthreads();

        // radix-select k-th smallest (4x8-bit)
        unsigned prefix = 0; int kk = k;
        for (int shift = 24; shift >= 0; shift -= 8) {
            hist[tid] = 0;
            __syncthreads();
            unsigned pmask = (shift == 24) ? 0u : (0xFFFFFFFFu << (shift + 8));
            for (int i = tid; i < N_ANCH; i += NT) {
                unsigned key = fkey(A[i]);
                if ((key & pmask) == prefix) atomicAdd(&hist[(key >> shift) & 255], 1);
            }
            __syncthreads();
            int c = hist[tid];
            int inc = wscan_incl(c, l);
            if (l == 31) iw[wid] = inc;
            __syncthreads();
            int off = 0;
            #pragma unroll
            for (int w = 0; w < 8; ++w) if (w < wid) off += iw[w];
            int incl = inc + off;
            if (incl >= kk && incl - c < kk) { si2[0] = tid; si2[1] = kk - (incl - c); }
            __syncthreads();
            prefix |= ((unsigned)si2[0]) << shift;
            kk = si2[1];
            __syncthreads();
        }
        const unsigned T = prefix;
        const int rties = kk;

        // deterministic compaction
        int cnt = 0;
        for (int i = tid; i < N_ANCH; i += NT) {
            unsigned key = fkey(A[i]);
            bool pick = key < T;
            if (key == T) {
                int tr = 0;
                for (int j = 0; j < i; ++j) if (fkey(A[j]) == T) ++tr;
                pick = (tr < rties);
            }
            if (pick) ++cnt;
        }
        {
            int inc = wscan_incl(cnt, l);
            if (l == 31) iw[wid] = inc;
            __syncthreads();
            int off = 0;
            #pragma unroll
            for (int w = 0; w < 8; ++w) if (w < wid) off += iw[w];
            int o = off + inc - cnt;
            for (int i = tid; i < N_ANCH; i += NT) {
                unsigned key = fkey(A[i]);
                bool pick = key < T;
                if (key == T) {
                    int tr = 0;
                    for (int j = 0; j < i; ++j) if (fkey(A[j]) == T) ++tr;
                    pick = (tr < rties);
                }
                if (pick) sel[o++] = i;
            }
        }
        __syncthreads();

        // stage-2 pass 1: colnorm squares over cols 2..5
        float q2 = 0.f, q3 = 0.f, q4 = 0.f, q5 = 0.f;
        if (tid < k) {
            const float* row = feat + (size_t)sel[tid] * N_FEAT;
            float a = row[2], b = row[3], c2 = row[4], d = row[5];
            q2 = a * a; q3 = b * b; q4 = c2 * c2; q5 = d * d;
        }
        {
            float v;
            v = wsum(q2); if (l == 0) wred[0 * 8 + wid] = v;
            v = wsum(q3); if (l == 0) wred[1 * 8 + wid] = v;
            v = wsum(q4); if (l == 0) wred[2 * 8 + wid] = v;
            v = wsum(q5); if (l == 0) wred[3 * 8 + wid] = v;
            __syncthreads();
            if (tid < 4) {
                float r = 0.f;
                for (int w = 0; w < 8; ++w) r += wred[tid * 8 + w];
                bres2[tid] = r;
            }
            __syncthreads();
        }
        const float den2 = fmaxf(sqrtf(bres2[0] + spl[2] * spl[2]), 1e-12f);
        const float den3 = fmaxf(sqrtf(bres2[1] + spl[3] * spl[3]), 1e-12f);
        const float den4 = fmaxf(sqrtf(bres2[2] + spl[4] * spl[4]), 1e-12f);
        const float den5 = fmaxf(sqrtf(bres2[3] + spl[5] * spl[5]), 1e-12f);

        // stage-2 pass 2: sl1 / focal / liou over selected rows
        float lsl1 = 0.f, lfl = 0.f, lll = 0.f;
        const int tgt = (p1 > p0) ? 1 : 0;
        if (tid < k) {
            const float* row = feat + (size_t)sel[tid] * N_FEAT;
            float sacc = 0.f, dd, ad;
            dd = row[2] / den2 - spl[2] / den2; ad = fabsf(dd);
            sacc += (ad < 1.f) ? 0.5f * dd * dd : ad - 0.5f;
            dd = row[3] / den3 - spl[3] / den3; ad = fabsf(dd);
            sacc += (ad < 1.f) ? 0.5f * dd * dd : ad - 0.5f;
            dd = row[4] / den4 - spl[4] / den4; ad = fabsf(dd);
            sacc += (ad < 1.f) ? 0.5f * dd * dd : ad - 0.5f;
            dd = row[5] / den5 - spl[5] / den5; ad = fabsf(dd);
            sacc += (ad < 1.f) ? 0.5f * dd * dd : ad - 0.5f;
            lsl1 = sacc * 0.25f;
            float x0 = row[0], x1 = row[1];
            float mx = fmaxf(x0, x1);
            float lse = mx + logf(expf(x0 - mx) + expf(x1 - mx));
            float logpt = (tgt ? x1 : x0) - lse;
            float pt = expf(logpt);
            lfl = -(1.f - pt) * (1.f - pt) * logpt;
            float L = 0.f;
            #pragma unroll 12
            for (int j = 6; j < 78; ++j) L += fabsf(row[j] - spl[j]);
            lll = 1.f - (2160.f - L) / (2160.f + L + 1e-9f);
        }
        {
            float v;
            v = wsum(lsl1); if (l == 0) wred[0 * 8 + wid] = v;
            v = wsum(lll);  if (l == 0) wred[1 * 8 + wid] = v;
            v = wsum(lfl);  if (l == 0) wred[2 * 8 + wid] = v;
            __syncthreads();
            if (tid == 0) {
                float ra = 0.f, rb = 0.f, rc = 0.f;
                for (int w = 0; w < 8; ++w) {
                    ra += wred[0 * 8 + w]; rb += wred[1 * 8 + w]; rc += wred[2 * 8 + w];
                }
                float invk = 1.f / (float)k;
                int task = img * 16 + pair * LPC + l2;
                g_part[task * 3 + 0] = ra * invk;
                g_part[task * 3 + 1] = rb * invk;
                g_part[task * 3 + 2] = rc * invk;
            }
            __syncthreads();
        }
    }

    // ---------------- last-CTA final fold
    if (tid == 0) {
        __threadfence();
        unsigned v = atomicAdd(&g_ctr, 1u);
        sAm = (v == NCTA - 1) ? 1u : 0u;
    }
    __syncthreads();
    if (sAm) {
        if (tid == 0) g_ctr = 0;
        __threadfence();
        float a = 0.f, b = 0.f, c = 0.f;
        for (int i = tid; i < 1024; i += NT) {
            a += g_part[i * 3 + 0];
            b += g_part[i * 3 + 1];
            c += g_part[i * 3 + 2];
        }
        float v;
        v = wsum(a); if (l == 0) wred[0 * 8 + wid] = v;
        v = wsum(b); if (l == 0) wred[1 * 8 + wid] = v;
        v = wsum(c); if (l == 0) wred[2 * 8 + wid] = v;
        __syncthreads();
        if (tid == 0) {
            float sa = 0.f, sb = 0.f, sc = 0.f;
            for (int w = 0; w < 8; ++w) {
                sa += wred[0 * 8 + w]; sb += wred[1 * 8 + w]; sc += wred[2 * 8 + w];
            }
            const float inv = 1.f / 1024.f;
            float sl1l = sa * inv, ll = sb * inv, fl = sc * inv;
            out[0] = (sl1l > 0.f ? 0.5f * sl1l : 0.f)
                   + (ll   > 0.f ? 2.0f * ll   : 0.f)
                   + (fl   > 0.f ? 2.0f * fl   : 0.f);
        }
    }
}

extern "C" void kernel_launch(void* const* d_in, const int* in_sizes, int n_in,
                              void* d_out, int out_size)
{
    const float* output = (const float*)d_in[0];  // [64,1000,78]
    const float* label  = (const float*)d_in[1];  // [64,16,78]
    lane_kernel<<<NCTA, NT>>>(output, label, (float*)d_out);
}

// round 7
// speedup vs baseline: 1.6627x; 1.6627x over previous
#include <cuda_runtime.h>

#define N_ANCH 1000
#define N_FEAT 78
#define NT     256
#define LPC    2
#define NCTA   512          // 64 images * 8 CTAs (2 priors each)
#define K_MAX  64
#define FULL   0xffffffffu
#define SPSTR  80
#define NIMG   64

__device__ float    g_featT[(size_t)NIMG * N_FEAT * N_ANCH];  // [img][j][i]
__device__ float    g_part[1024 * 3];
__device__ unsigned g_ctr;

static __device__ __forceinline__ unsigned fkey(float f) {
    unsigned u = __float_as_uint(f);
    return (u & 0x80000000u) ? ~u : (u | 0x80000000u);
}
static __device__ __forceinline__ float wsum(float v) {
    #pragma unroll
    for (int o = 16; o; o >>= 1) v += __shfl_xor_sync(FULL, v, o);
    return v;
}
static __device__ __forceinline__ float wmax(float v) {
    #pragma unroll
    for (int o = 16; o; o >>= 1) v = fmaxf(v, __shfl_xor_sync(FULL, v, o));
    return v;
}
static __device__ __forceinline__ int wscan_incl(int v, int lane) {
    #pragma unroll
    for (int o = 1; o < 32; o <<= 1) {
        int t = __shfl_up_sync(FULL, v, o);
        if (lane >= o) v += t;
    }
    return v;
}

// ---------------- transpose: output[img][i][j] -> g_featT[img][j][i]
__global__ __launch_bounds__(NT)
void transpose_kernel(const float* __restrict__ output)
{
    __shared__ float t[N_FEAT][33];
    const int tid = threadIdx.x;
    const int img = blockIdx.x >> 5;
    const int ib  = blockIdx.x & 31;
    const int ibase = ib * 32;
    const int cnt = (N_ANCH - ibase < 32) ? (N_ANCH - ibase) : 32;

    const float* src = output + ((size_t)img * N_ANCH + ibase) * N_FEAT;
    for (int idx = tid; idx < cnt * N_FEAT; idx += NT) {
        int r = idx / N_FEAT, c = idx - r * N_FEAT;
        t[c][r] = src[idx];
    }
    __syncthreads();
    float* dst = g_featT + (size_t)img * (N_FEAT * N_ANCH);
    for (int idx = tid; idx < N_FEAT * 32; idx += NT) {
        int j = idx >> 5, ii = idx & 31;
        if (ii < cnt) dst[j * N_ANCH + ibase + ii] = t[j][ii];
    }
}

__global__ __launch_bounds__(NT, 4)
void lane_kernel(const float* __restrict__ output, const float* __restrict__ label,
                 float* __restrict__ out)
{
    __shared__ __align__(16) float A0[N_ANCH];
    __shared__ __align__(16) float A1[N_ANCH];
    __shared__ __align__(16) float c0s[N_ANCH];
    __shared__ __align__(16) float c1s[N_ANCH];
    __shared__ float spsm[LPC * SPSTR];
    __shared__ float wred[12 * 8];
    __shared__ int   iw[8];
    __shared__ int   hist[256];
    __shared__ int   sel[K_MAX];
    __shared__ int   si2[2];
    __shared__ float bres[12];
    __shared__ float bres2[4];
    __shared__ unsigned sAm;

    const int tid = threadIdx.x;
    const int wid = tid >> 5;
    const int l   = tid & 31;
    const int bx   = blockIdx.x;
    const int img  = bx >> 3;
    const int pair = bx & 7;
    const float* ft   = g_featT + (size_t)img * (N_FEAT * N_ANCH);
    const float* feat = output + (size_t)img * (N_ANCH * N_FEAT);

    for (int idx = tid; idx < LPC * N_FEAT; idx += NT) {
        int ll = idx / N_FEAT, j = idx - ll * N_FEAT;
        spsm[ll * SPSTR + j] = label[((size_t)img * 16 + pair * LPC + ll) * N_FEAT + j];
    }
    __syncthreads();

    const bool act = (tid < 250);
    const int  i0  = tid * 4;

    // ---------------- L1 accumulation: thread owns 4 anchors, float4 coalesced
    float La0 = 0.f, La1 = 0.f, La2 = 0.f, La3 = 0.f;
    float Lb0 = 0.f, Lb1 = 0.f, Lb2 = 0.f, Lb3 = 0.f;
    if (act) {
        #pragma unroll 8
        for (int j = 6; j < 78; ++j) {
            float4 v = ((const float4*)(ft + j * N_ANCH))[tid];
            float s0 = spsm[j], s1 = spsm[SPSTR + j];
            La0 += fabsf(v.x - s0); La1 += fabsf(v.y - s0);
            La2 += fabsf(v.z - s0); La3 += fabsf(v.w - s0);
            Lb0 += fabsf(v.x - s1); Lb1 += fabsf(v.y - s1);
            Lb2 += fabsf(v.z - s1); Lb3 += fabsf(v.w - s1);
        }
    }

    // ---------------- header cols + per-anchor stage-1 quantities
    float m0 = -3.4e38f, m1 = -3.4e38f;
    float a0 = 0.f, a1 = 0.f, a2 = 0.f, a3 = 0.f;
    float a4 = 0.f, a5 = 0.f, a6 = 0.f, a7 = 0.f;
    if (act) {
        float4 lg0 = ((const float4*)(ft + 0 * N_ANCH))[tid];
        float4 lg1 = ((const float4*)(ft + 1 * N_ANCH))[tid];
        float4 rxv = ((const float4*)(ft + 3 * N_ANCH))[tid];
        float4 ryv = ((const float4*)(ft + 4 * N_ANCH))[tid];
        float4 rtv = ((const float4*)(ft + 5 * N_ANCH))[tid];
        ((float4*)c0s)[tid] = lg0;
        ((float4*)c1s)[tid] = lg1;
        m0 = fmaxf(fmaxf(lg0.x, lg0.y), fmaxf(lg0.z, lg0.w));
        m1 = fmaxf(fmaxf(lg1.x, lg1.y), fmaxf(lg1.z, lg1.w));
        const float p0x = spsm[3], p0y = spsm[4], p0t = spsm[5];
        const float p1x = spsm[SPSTR + 3], p1y = spsm[SPSTR + 4], p1t = spsm[SPSTR + 5];
        float rA[4], rB[4];
        const float rx[4] = {rxv.x, rxv.y, rxv.z, rxv.w};
        const float ry[4] = {ryv.x, ryv.y, ryv.z, ryv.w};
        const float rt[4] = {rtv.x, rtv.y, rtv.z, rtv.w};
        const float Las[4] = {La0, La1, La2, La3};
        const float Lbs[4] = {Lb0, Lb1, Lb2, Lb3};
        #pragma unroll
        for (int a = 0; a < 4; ++a) {
            {
                float dx = rx[a] - p0x, dy = ry[a] - p0y, th = rt[a] - p0t;
                float xy = sqrtf(dx * dx + dy * dy);
                float L = Las[a];
                float dis = L * (1.0f / 72.0f);
                float liou = 1.f - (2160.f - L) / (2160.f + L + 1e-9f);
                rA[a] = dis * xy * th;
                a0 += xy * xy; a1 += th * th; a2 += dis * dis; a3 += liou;
            }
            {
                float dx = rx[a] - p1x, dy = ry[a] - p1y, th = rt[a] - p1t;
                float xy = sqrtf(dx * dx + dy * dy);
                float L = Lbs[a];
                float dis = L * (1.0f / 72.0f);
                float liou = 1.f - (2160.f - L) / (2160.f + L + 1e-9f);
                rB[a] = dis * xy * th;
                a4 += xy * xy; a5 += th * th; a6 += dis * dis; a7 += liou;
            }
        }
        ((float4*)A0)[tid] = make_float4(rA[0], rA[1], rA[2], rA[3]);
        ((float4*)A1)[tid] = make_float4(rB[0], rB[1], rB[2], rB[3]);
    }

    // ---------------- block-reduce 10 quantities
    {
        float v;
        v = wmax(m0); if (l == 0) wred[0 * 8 + wid] = v;
        v = wmax(m1); if (l == 0) wred[1 * 8 + wid] = v;
        v = wsum(a0); if (l == 0) wred[2 * 8 + wid] = v;
        v = wsum(a1); if (l == 0) wred[3 * 8 + wid] = v;
        v = wsum(a2); if (l == 0) wred[4 * 8 + wid] = v;
        v = wsum(a3); if (l == 0) wred[5 * 8 + wid] = v;
        v = wsum(a4); if (l == 0) wred[6 * 8 + wid] = v;
        v = wsum(a5); if (l == 0) wred[7 * 8 + wid] = v;
        v = wsum(a6); if (l == 0) wred[8 * 8 + wid] = v;
        v = wsum(a7); if (l == 0) wred[9 * 8 + wid] = v;
        __syncthreads();
        if (tid < 10) {
            float r = wred[tid * 8];
            if (tid < 2) { for (int w = 1; w < 8; ++w) r = fmaxf(r, wred[tid * 8 + w]); }
            else         { for (int w = 1; w < 8; ++w) r += wred[tid * 8 + w]; }
            bres[tid] = r;
        }
        __syncthreads();
    }
    const float M0 = bres[0], M1 = bres[1];

    // ---------------- softmax sums
    float s0 = 0.f, s1 = 0.f;
    if (act) {
        float4 c = ((const float4*)c0s)[tid];
        s0 = expf(c.x - M0) + expf(c.y - M0) + expf(c.z - M0) + expf(c.w - M0);
        float4 d = ((const float4*)c1s)[tid];
        s1 = expf(d.x - M1) + expf(d.y - M1) + expf(d.z - M1) + expf(d.w - M1);
    }
    {
        float v;
        v = wsum(s0); if (l == 0) wred[0 * 8 + wid] = v;
        v = wsum(s1); if (l == 0) wred[1 * 8 + wid] = v;
        __syncthreads();
        if (tid < 2) {
            float r = 0.f;
            for (int w = 0; w < 8; ++w) r += wred[tid * 8 + w];
            bres[tid] = r;
        }
        __syncthreads();
    }
    const float lse0 = M0 + logf(bres[0]);
    const float lse1 = M1 + logf(bres[1]);

    // ---------------- focal factors (feature-only)
    if (act) {
        float4 c = ((const float4*)c0s)[tid];
        float ls, e;
        ls = c.x - lse0; e = expf(ls); c.x = (1.f - e) * (1.f - e) * ls;
        ls = c.y - lse0; e = expf(ls); c.y = (1.f - e) * (1.f - e) * ls;
        ls = c.z - lse0; e = expf(ls); c.z = (1.f - e) * (1.f - e) * ls;
        ls = c.w - lse0; e = expf(ls); c.w = (1.f - e) * (1.f - e) * ls;
        ((float4*)c0s)[tid] = c;
        float4 d = ((const float4*)c1s)[tid];
        ls = d.x - lse1; e = expf(ls); d.x = (1.f - e) * (1.f - e) * ls;
        ls = d.y - lse1; e = expf(ls); d.y = (1.f - e) * (1.f - e) * ls;
        ls = d.z - lse1; e = expf(ls); d.z = (1.f - e) * (1.f - e) * ls;
        ls = d.w - lse1; e = expf(ls); d.w = (1.f - e) * (1.f - e) * ls;
        ((float4*)c1s)[tid] = d;
    }
    __syncthreads();

    // ---------------- per-prior: cost finalize, radix-select, stage-2
    for (int l2 = 0; l2 < LPC; ++l2) {
        const float sxy   = bres[2 + l2 * 4 + 0];
        const float sth   = bres[2 + l2 * 4 + 1];
        const float sdis  = bres[2 + l2 * 4 + 2];
        const float sliou = bres[2 + l2 * 4 + 3];
        const float Nx  = fmaxf(sqrtf(sxy),  1e-12f);
        const float Nt2 = fmaxf(sqrtf(sth),  1e-12f);
        const float Nd  = fmaxf(sqrtf(sdis), 1e-12f);
        const float invn = 1.f / (Nx * Nt2 * Nd);
        int k = (int)sliou;
        if (k < 1) k = 1;
        if (k > K_MAX) k = K_MAX;
        const float* spl = spsm + l2 * SPSTR;
        const float p0 = spl[0], p1 = spl[1];
        float* A = l2 ? A1 : A0;

        if (act) {
            float4 a = ((const float4*)A)[tid];
            float4 f0 = ((const float4*)c0s)[tid];
            float4 f1 = ((const float4*)c1s)[tid];
            float t;
            t = a.x * invn; a.x = 3.f * t * t + p0 * f0.x + p1 * f1.x;
            t = a.y * invn; a.y = 3.f * t * t + p0 * f0.y + p1 * f1.y;
            t = a.z * invn; a.z = 3.f * t * t + p0 * f0.z + p1 * f1.z;
            t = a.w * invn; a.w = 3.f * t * t + p0 * f0.w + p1 * f1.w;
            ((float4*)A)[tid] = a;
        }
        __syncthreads();

        // radix-select k-th smallest (4x8-bit)
        unsigned prefix = 0; int kk = k;
        for (int shift = 24; shift >= 0; shift -= 8) {
            hist[tid] = 0;
            __syncthreads();
            unsigned pmask = (shift == 24) ? 0u : (0xFFFFFFFFu << (shift + 8));
            for (int i = tid; i < N_ANCH; i += NT) {
                unsigned key = fkey(A[i]);
                if ((key & pmask) == prefix) atomicAdd(&hist[(key >> shift) & 255], 1);
            }
            __syncthreads();
            int c = hist[tid];
            int inc = wscan_incl(c, l);
            if (l == 31) iw[wid] = inc;
            __syncthreads();
            int off = 0;
            #pragma unroll
            for (int w = 0; w < 8; ++w) if (w < wid) off += iw[w];
            int incl = inc + off;
            if (incl >= kk && incl - c < kk) { si2[0] = tid; si2[1] = kk - (incl - c); }
            __syncthreads();
            prefix |= ((unsigned)si2[0]) << shift;
            kk = si2[1];
            __syncthreads();
        }
        const unsigned T = prefix;
        const int rties = kk;

        // deterministic compaction
        int cnt = 0;
        for (int i = tid; i < N_ANCH; i += NT) {
            unsigned key = fkey(A[i]);
            bool pick = key < T;
            if (key == T) {
                int tr = 0;
                for (int j = 0; j < i; ++j) if (fkey(A[j]) == T) ++tr;
                pick = (tr < rties);
            }
            if (pick) ++cnt;
        }
        {
            int inc = wscan_incl(cnt, l);
            if (l == 31) iw[wid] = inc;
            __syncthreads();
            int off = 0;
            #pragma unroll
            for (int w = 0; w < 8; ++w) if (w < wid) off += iw[w];
            int o = off + inc - cnt;
            for (int i = tid; i < N_ANCH; i += NT) {
                unsigned key = fkey(A[i]);
                bool pick = key < T;
                if (key == T) {
                    int tr = 0;
                    for (int j = 0; j < i; ++j) if (fkey(A[j]) == T) ++tr;
                    pick = (tr < rties);
                }
                if (pick) sel[o++] = i;
            }
        }
        __syncthreads();

        // stage-2 pass 1: colnorm squares over cols 2..5
        float q2 = 0.f, q3 = 0.f, q4 = 0.f, q5 = 0.f;
        if (tid < k) {
            const float* row = feat + (size_t)sel[tid] * N_FEAT;
            float a = row[2], b = row[3], c2 = row[4], d = row[5];
            q2 = a * a; q3 = b * b; q4 = c2 * c2; q5 = d * d;
        }
        {
            float v;
            v = wsum(q2); if (l == 0) wred[0 * 8 + wid] = v;
            v = wsum(q3); if (l == 0) wred[1 * 8 + wid] = v;
            v = wsum(q4); if (l == 0) wred[2 * 8 + wid] = v;
            v = wsum(q5); if (l == 0) wred[3 * 8 + wid] = v;
            __syncthreads();
            if (tid < 4) {
                float r = 0.f;
                for (int w = 0; w < 8; ++w) r += wred[tid * 8 + w];
                bres2[tid] = r;
            }
            __syncthreads();
        }
        const float den2 = fmaxf(sqrtf(bres2[0] + spl[2] * spl[2]), 1e-12f);
        const float den3 = fmaxf(sqrtf(bres2[1] + spl[3] * spl[3]), 1e-12f);
        const float den4 = fmaxf(sqrtf(bres2[2] + spl[4] * spl[4]), 1e-12f);
        const float den5 = fmaxf(sqrtf(bres2[3] + spl[5] * spl[5]), 1e-12f);

        // stage-2 pass 2: sl1 / focal / liou over selected rows
        float lsl1 = 0.f, lfl = 0.f, lll = 0.f;
        const int tgt = (p1 > p0) ? 1 : 0;
        if (tid < k) {
            const float* row = feat + (size_t)sel[tid] * N_FEAT;
            float sacc = 0.f, dd, ad;
            dd = row[2] / den2 - spl[2] / den2; ad = fabsf(dd);
            sacc += (ad < 1.f) ? 0.5f * dd * dd : ad - 0.5f;
            dd = row[3] / den3 - spl[3] / den3; ad = fabsf(dd);
            sacc += (ad < 1.f) ? 0.5f * dd * dd : ad - 0.5f;
            dd = row[4] / den4 - spl[4] / den4; ad = fabsf(dd);
            sacc += (ad < 1.f) ? 0.5f * dd * dd : ad - 0.5f;
            dd = row[5] / den5 - spl[5] / den5; ad = fabsf(dd);
            sacc += (ad < 1.f) ? 0.5f * dd * dd : ad - 0.5f;
            lsl1 = sacc * 0.25f;
            float x0 = row[0], x1 = row[1];
            float mx = fmaxf(x0, x1);
            float lse = mx + logf(expf(x0 - mx) + expf(x1 - mx));
            float logpt = (tgt ? x1 : x0) - lse;
            float pt = expf(logpt);
            lfl = -(1.f - pt) * (1.f - pt) * logpt;
            float L = 0.f;
            #pragma unroll 12
            for (int j = 6; j < 78; ++j) L += fabsf(row[j] - spl[j]);
            lll = 1.f - (2160.f - L) / (2160.f + L + 1e-9f);
        }
        {
            float v;
            v = wsum(lsl1); if (l == 0) wred[0 * 8 + wid] = v;
            v = wsum(lll);  if (l == 0) wred[1 * 8 + wid] = v;
            v = wsum(lfl);  if (l == 0) wred[2 * 8 + wid] = v;
            __syncthreads();
            if (tid == 0) {
                float ra = 0.f, rb = 0.f, rc = 0.f;
                for (int w = 0; w < 8; ++w) {
                    ra += wred[0 * 8 + w]; rb += wred[1 * 8 + w]; rc += wred[2 * 8 + w];
                }
                float invk = 1.f / (float)k;
                int task = img * 16 + pair * LPC + l2;
                g_part[task * 3 + 0] = ra * invk;
                g_part[task * 3 + 1] = rb * invk;
                g_part[task * 3 + 2] = rc * invk;
            }
            __syncthreads();
        }
    }

    // ---------------- last-CTA final fold
    if (tid == 0) {
        __threadfence();
        unsigned v = atomicAdd(&g_ctr, 1u);
        sAm = (v == NCTA - 1) ? 1u : 0u;
    }
    __syncthreads();
    if (sAm) {
        if (tid == 0) g_ctr = 0;
        __threadfence();
        float a = 0.f, b = 0.f, c = 0.f;
        for (int i = tid; i < 1024; i += NT) {
            a += g_part[i * 3 + 0];
            b += g_part[i * 3 + 1];
            c += g_part[i * 3 + 2];
        }
        float v;
        v = wsum(a); if (l == 0) wred[0 * 8 + wid] = v;
        v = wsum(b); if (l == 0) wred[1 * 8 + wid] = v;
        v = wsum(c); if (l == 0) wred[2 * 8 + wid] = v;
        __syncthreads();
        if (tid == 0) {
            float sa = 0.f, sb = 0.f, sc = 0.f;
            for (int w = 0; w < 8; ++w) {
                sa += wred[0 * 8 + w]; sb += wred[1 * 8 + w]; sc += wred[2 * 8 + w];
            }
            const float inv = 1.f / 1024.f;
            float sl1l = sa * inv, ll = sb * inv, fl = sc * inv;
            out[0] = (sl1l > 0.f ? 0.5f * sl1l : 0.f)
                   + (ll   > 0.f ? 2.0f * ll   : 0.f)
                   + (fl   > 0.f ? 2.0f * fl   : 0.f);
        }
    }
}

extern "C" void kernel_launch(void* const* d_in, const int* in_sizes, int n_in,
                              void* d_out, int out_size)
{
    const float* output = (const float*)d_in[0];  // [64,1000,78]
    const float* label  = (const float*)d_in[1];  // [64,16,78]
    transpose_kernel<<<NIMG * 32, NT>>>(output);
    lane_kernel<<<NCTA, NT>>>(output, label, (float*)d_out);
}

// round 8
// speedup vs baseline: 3.8069x; 2.2896x over previous
#include <cuda_runtime.h>

#define N_ANCH 1000
#define N_FEAT 78
#define NT     256
#define NCTA   512          // 64 images * 8 CTAs (2 priors each)
#define K_MAX  64
#define FULL   0xffffffffu
#define SPSTR  80
#define NIMG   64

__device__ float    g_featT[(size_t)NIMG * N_FEAT * N_ANCH];  // [img][j][i]
__device__ float    g_part[1024 * 3];
__device__ unsigned g_ctr;

static __device__ __forceinline__ unsigned fkey(float f) {
    unsigned u = __float_as_uint(f);
    return (u & 0x80000000u) ? ~u : (u | 0x80000000u);
}
static __device__ __forceinline__ float wsum(float v) {
    #pragma unroll
    for (int o = 16; o; o >>= 1) v += __shfl_xor_sync(FULL, v, o);
    return v;
}
static __device__ __forceinline__ float wmax(float v) {
    #pragma unroll
    for (int o = 16; o; o >>= 1) v = fmaxf(v, __shfl_xor_sync(FULL, v, o));
    return v;
}
static __device__ __forceinline__ int wscan_incl(int v, int lane) {
    #pragma unroll
    for (int o = 1; o < 32; o <<= 1) {
        int t = __shfl_up_sync(FULL, v, o);
        if (lane >= o) v += t;
    }
    return v;
}

// ---------------- transpose: output[img][i][j] -> g_featT[img][j][i]
__global__ __launch_bounds__(NT)
void transpose_kernel(const float* __restrict__ output)
{
    __shared__ float t[N_FEAT][33];
    const int tid = threadIdx.x;
    const int img = blockIdx.x >> 5;
    const int ib  = blockIdx.x & 31;
    const int ibase = ib * 32;
    const int cnt = (N_ANCH - ibase < 32) ? (N_ANCH - ibase) : 32;

    const float* src = output + ((size_t)img * N_ANCH + ibase) * N_FEAT;
    for (int idx = tid; idx < cnt * N_FEAT; idx += NT) {
        int r = idx / N_FEAT, c = idx - r * N_FEAT;
        t[c][r] = src[idx];
    }
    __syncthreads();
    float* dst = g_featT + (size_t)img * (N_FEAT * N_ANCH);
    for (int idx = tid; idx < N_FEAT * 32; idx += NT) {
        int j = idx >> 5, ii = idx & 31;
        if (ii < cnt) dst[j * N_ANCH + ibase + ii] = t[j][ii];
    }
}

#define GBAR() asm volatile("bar.sync %0, 128;" :: "r"(wg + 1) : "memory")

__global__ __launch_bounds__(NT, 4)
void lane_kernel(const float* __restrict__ output, const float* __restrict__ label,
                 float* __restrict__ out)
{
    __shared__ __align__(16) float A0[N_ANCH];
    __shared__ __align__(16) float A1[N_ANCH];
    __shared__ __align__(16) float c0s[N_ANCH];
    __shared__ __align__(16) float c1s[N_ANCH];
    __shared__ float spsm[2 * SPSTR];
    __shared__ float wred[12 * 8];
    __shared__ float bres[12];
    __shared__ unsigned sAm;
    // per-group (per-prior) scratch
    __shared__ int   hist2[2][256];
    __shared__ int   iw2[2][4];
    __shared__ int   sel2[2][K_MAX];
    __shared__ int   si22[2][2];
    __shared__ float wred2[2][16];
    __shared__ float bres22[2][4];
    __shared__ int   tbuf[2][64];
    __shared__ int   tcnt[2];

    const int tid = threadIdx.x;
    const int wid = tid >> 5;
    const int l   = tid & 31;
    const int bx   = blockIdx.x;
    const int img  = bx >> 3;
    const int pair = bx & 7;
    const float* ft   = g_featT + (size_t)img * (N_FEAT * N_ANCH);
    const float* feat = output + (size_t)img * (N_ANCH * N_FEAT);

    for (int idx = tid; idx < 2 * N_FEAT; idx += NT) {
        int ll = idx / N_FEAT, j = idx - ll * N_FEAT;
        spsm[ll * SPSTR + j] = label[((size_t)img * 16 + pair * 2 + ll) * N_FEAT + j];
    }
    __syncthreads();

    const bool act = (tid < 250);

    // ---------------- L1 accumulation: thread owns 4 anchors, float4 coalesced
    float La0 = 0.f, La1 = 0.f, La2 = 0.f, La3 = 0.f;
    float Lb0 = 0.f, Lb1 = 0.f, Lb2 = 0.f, Lb3 = 0.f;
    if (act) {
        #pragma unroll 8
        for (int j = 6; j < 78; ++j) {
            float4 v = ((const float4*)(ft + j * N_ANCH))[tid];
            float s0 = spsm[j], s1 = spsm[SPSTR + j];
            La0 += fabsf(v.x - s0); La1 += fabsf(v.y - s0);
            La2 += fabsf(v.z - s0); La3 += fabsf(v.w - s0);
            Lb0 += fabsf(v.x - s1); Lb1 += fabsf(v.y - s1);
            Lb2 += fabsf(v.z - s1); Lb3 += fabsf(v.w - s1);
        }
    }

    // ---------------- header cols + per-anchor stage-1 quantities
    float m0 = -3.4e38f, m1 = -3.4e38f;
    float a0 = 0.f, a1 = 0.f, a2 = 0.f, a3 = 0.f;
    float a4 = 0.f, a5 = 0.f, a6 = 0.f, a7 = 0.f;
    if (act) {
        float4 lg0 = ((const float4*)(ft + 0 * N_ANCH))[tid];
        float4 lg1 = ((const float4*)(ft + 1 * N_ANCH))[tid];
        float4 rxv = ((const float4*)(ft + 3 * N_ANCH))[tid];
        float4 ryv = ((const float4*)(ft + 4 * N_ANCH))[tid];
        float4 rtv = ((const float4*)(ft + 5 * N_ANCH))[tid];
        ((float4*)c0s)[tid] = lg0;
        ((float4*)c1s)[tid] = lg1;
        m0 = fmaxf(fmaxf(lg0.x, lg0.y), fmaxf(lg0.z, lg0.w));
        m1 = fmaxf(fmaxf(lg1.x, lg1.y), fmaxf(lg1.z, lg1.w));
        const float p0x = spsm[3], p0y = spsm[4], p0t = spsm[5];
        const float p1x = spsm[SPSTR + 3], p1y = spsm[SPSTR + 4], p1t = spsm[SPSTR + 5];
        float rA[4], rB[4];
        const float rx[4] = {rxv.x, rxv.y, rxv.z, rxv.w};
        const float ry[4] = {ryv.x, ryv.y, ryv.z, ryv.w};
        const float rt[4] = {rtv.x, rtv.y, rtv.z, rtv.w};
        const float Las[4] = {La0, La1, La2, La3};
        const float Lbs[4] = {Lb0, Lb1, Lb2, Lb3};
        #pragma unroll
        for (int a = 0; a < 4; ++a) {
            {
                float dx = rx[a] - p0x, dy = ry[a] - p0y, th = rt[a] - p0t;
                float xy = sqrtf(dx * dx + dy * dy);
                float L = Las[a];
                float dis = L * (1.0f / 72.0f);
                float liou = 1.f - (2160.f - L) / (2160.f + L + 1e-9f);
                rA[a] = dis * xy * th;
                a0 += xy * xy; a1 += th * th; a2 += dis * dis; a3 += liou;
            }
            {
                float dx = rx[a] - p1x, dy = ry[a] - p1y, th = rt[a] - p1t;
                float xy = sqrtf(dx * dx + dy * dy);
                float L = Lbs[a];
                float dis = L * (1.0f / 72.0f);
                float liou = 1.f - (2160.f - L) / (2160.f + L + 1e-9f);
                rB[a] = dis * xy * th;
                a4 += xy * xy; a5 += th * th; a6 += dis * dis; a7 += liou;
            }
        }
        ((float4*)A0)[tid] = make_float4(rA[0], rA[1], rA[2], rA[3]);
        ((float4*)A1)[tid] = make_float4(rB[0], rB[1], rB[2], rB[3]);
    }

    // ---------------- block-reduce 10 quantities
    {
        float v;
        v = wmax(m0); if (l == 0) wred[0 * 8 + wid] = v;
        v = wmax(m1); if (l == 0) wred[1 * 8 + wid] = v;
        v = wsum(a0); if (l == 0) wred[2 * 8 + wid] = v;
        v = wsum(a1); if (l == 0) wred[3 * 8 + wid] = v;
        v = wsum(a2); if (l == 0) wred[4 * 8 + wid] = v;
        v = wsum(a3); if (l == 0) wred[5 * 8 + wid] = v;
        v = wsum(a4); if (l == 0) wred[6 * 8 + wid] = v;
        v = wsum(a5); if (l == 0) wred[7 * 8 + wid] = v;
        v = wsum(a6); if (l == 0) wred[8 * 8 + wid] = v;
        v = wsum(a7); if (l == 0) wred[9 * 8 + wid] = v;
        __syncthreads();
        if (tid < 10) {
            float r = wred[tid * 8];
            if (tid < 2) { for (int w = 1; w < 8; ++w) r = fmaxf(r, wred[tid * 8 + w]); }
            else         { for (int w = 1; w < 8; ++w) r += wred[tid * 8 + w]; }
            bres[tid] = r;
        }
        __syncthreads();
    }
    const float M0 = bres[0], M1 = bres[1];

    // ---------------- softmax sums
    float s0 = 0.f, s1 = 0.f;
    if (act) {
        float4 c = ((const float4*)c0s)[tid];
        s0 = expf(c.x - M0) + expf(c.y - M0) + expf(c.z - M0) + expf(c.w - M0);
        float4 d = ((const float4*)c1s)[tid];
        s1 = expf(d.x - M1) + expf(d.y - M1) + expf(d.z - M1) + expf(d.w - M1);
    }
    {
        float v;
        v = wsum(s0); if (l == 0) wred[0 * 8 + wid] = v;
        v = wsum(s1); if (l == 0) wred[1 * 8 + wid] = v;
        __syncthreads();
        if (tid < 2) {
            float r = 0.f;
            for (int w = 0; w < 8; ++w) r += wred[tid * 8 + w];
            bres[tid] = r;
        }
        __syncthreads();
    }
    const float lse0 = M0 + logf(bres[0]);
    const float lse1 = M1 + logf(bres[1]);

    // ---------------- focal factors (feature-only)
    if (act) {
        float4 c = ((const float4*)c0s)[tid];
        float ls, e;
        ls = c.x - lse0; e = expf(ls); c.x = (1.f - e) * (1.f - e) * ls;
        ls = c.y - lse0; e = expf(ls); c.y = (1.f - e) * (1.f - e) * ls;
        ls = c.z - lse0; e = expf(ls); c.z = (1.f - e) * (1.f - e) * ls;
        ls = c.w - lse0; e = expf(ls); c.w = (1.f - e) * (1.f - e) * ls;
        ((float4*)c0s)[tid] = c;
        float4 d = ((const float4*)c1s)[tid];
        ls = d.x - lse1; e = expf(ls); d.x = (1.f - e) * (1.f - e) * ls;
        ls = d.y - lse1; e = expf(ls); d.y = (1.f - e) * (1.f - e) * ls;
        ls = d.z - lse1; e = expf(ls); d.z = (1.f - e) * (1.f - e) * ls;
        ls = d.w - lse1; e = expf(ls); d.w = (1.f - e) * (1.f - e) * ls;
        ((float4*)c1s)[tid] = d;
    }
    __syncthreads();

    // ================ SPLIT: warps 0-3 handle prior 0, warps 4-7 prior 1 ======
    const int wg = wid >> 2;          // group (prior) id
    const int lt = tid & 127;         // thread id within group
    const int lw = (tid >> 5) & 3;    // warp id within group

    const float sxy   = bres[2 + wg * 4 + 0];
    const float sth   = bres[2 + wg * 4 + 1];
    const float sdis  = bres[2 + wg * 4 + 2];
    const float sliou = bres[2 + wg * 4 + 3];
    const float Nx  = fmaxf(sqrtf(sxy),  1e-12f);
    const float Nt2 = fmaxf(sqrtf(sth),  1e-12f);
    const float Nd  = fmaxf(sqrtf(sdis), 1e-12f);
    const float invn = 1.f / (Nx * Nt2 * Nd);
    int k = (int)sliou;
    if (k < 1) k = 1;
    if (k > K_MAX) k = K_MAX;
    const float* spl = spsm + wg * SPSTR;
    const float p0 = spl[0], p1 = spl[1];
    float* A = wg ? A1 : A0;

    // cost finalize (128 threads per group, float4 over 250 chunks)
    for (int i4 = lt; i4 < 250; i4 += 128) {
        float4 a = ((const float4*)A)[i4];
        float4 f0 = ((const float4*)c0s)[i4];
        float4 f1 = ((const float4*)c1s)[i4];
        float t;
        t = a.x * invn; a.x = 3.f * t * t + p0 * f0.x + p1 * f1.x;
        t = a.y * invn; a.y = 3.f * t * t + p0 * f0.y + p1 * f1.y;
        t = a.z * invn; a.z = 3.f * t * t + p0 * f0.z + p1 * f1.z;
        t = a.w * invn; a.w = 3.f * t * t + p0 * f0.w + p1 * f1.w;
        ((float4*)A)[i4] = a;
    }
    GBAR();

    // register-cache this thread's 8 keys (anchors lt, lt+128, ..., lt+896)
    unsigned keys[8];
    #pragma unroll
    for (int q = 0; q < 8; ++q) {
        int i = lt + (q << 7);
        keys[q] = (i < N_ANCH) ? fkey(A[i]) : 0xFFFFFFFFu;
    }

    // ---------------- radix-select k-th smallest (4x8-bit), 128 threads
    unsigned prefix = 0; int kk = k;
    for (int shift = 24; shift >= 0; shift -= 8) {
        hist2[wg][lt] = 0; hist2[wg][lt + 128] = 0;
        GBAR();
        unsigned pmask = (shift == 24) ? 0u : (0xFFFFFFFFu << (shift + 8));
        #pragma unroll
        for (int q = 0; q < 8; ++q) {
            int i = lt + (q << 7);
            if (i < N_ANCH && (keys[q] & pmask) == prefix)
                atomicAdd(&hist2[wg][(keys[q] >> shift) & 255], 1);
        }
        GBAR();
        int h0 = hist2[wg][2 * lt], h1 = hist2[wg][2 * lt + 1];
        int c = h0 + h1;
        int inc = wscan_incl(c, l);
        if (l == 31) iw2[wg][lw] = inc;
        GBAR();
        int off = 0;
        #pragma unroll
        for (int w = 0; w < 4; ++w) if (w < lw) off += iw2[wg][w];
        int incl = inc + off, excl = incl - c;
        if (excl < kk && kk <= incl) {
            if (kk <= excl + h0) { si22[wg][0] = 2 * lt;     si22[wg][1] = kk - excl; }
            else                 { si22[wg][0] = 2 * lt + 1; si22[wg][1] = kk - excl - h0; }
        }
        GBAR();
        prefix |= ((unsigned)si22[wg][0]) << shift;
        kk = si22[wg][1];
    }
    const unsigned T = prefix;
    const int rties = kk;             // first rties ties (by anchor index) at key T

    // ---------------- tie collection (small buffer, exact semantics)
    if (lt == 0) tcnt[wg] = 0;
    GBAR();
    #pragma unroll
    for (int q = 0; q < 8; ++q) {
        int i = lt + (q << 7);
        if (i < N_ANCH && keys[q] == T) {
            int p = atomicAdd(&tcnt[wg], 1);
            if (p < 64) tbuf[wg][p] = i;
        }
    }
    GBAR();
    const int nt = tcnt[wg];

    // pick(i): exact "first rties ties by index" semantics
    auto pick = [&](int q) -> bool {
        int i = lt + (q << 7);
        if (i >= N_ANCH) return false;
        unsigned key = keys[q];
        if (key < T) return true;
        if (key != T) return false;
        int r = 0;
        if (nt <= 64) {
            for (int t2 = 0; t2 < nt; ++t2) r += (tbuf[wg][t2] < i);
        } else {                      // pathological fallback (exact)
            for (int j = 0; j < i; ++j) r += (fkey(A[j]) == T);
        }
        return r < rties;
    };

    // ---------------- deterministic compaction (scan over 128 threads)
    int cnt = 0;
    #pragma unroll
    for (int q = 0; q < 8; ++q) cnt += pick(q) ? 1 : 0;
    {
        int inc = wscan_incl(cnt, l);
        if (l == 31) iw2[wg][lw] = inc;
        GBAR();
        int off = 0;
        #pragma unroll
        for (int w = 0; w < 4; ++w) if (w < lw) off += iw2[wg][w];
        int o = off + inc - cnt;
        #pragma unroll
        for (int q = 0; q < 8; ++q)
            if (pick(q)) sel2[wg][o++] = lt + (q << 7);
    }
    GBAR();

    // ---------------- stage-2 pass 1: colnorm squares over cols 2..5
    float q2 = 0.f, q3 = 0.f, q4 = 0.f, q5 = 0.f;
    if (lt < k) {
        const float* row = feat + (size_t)sel2[wg][lt] * N_FEAT;
        float a = row[2], b = row[3], c2 = row[4], d = row[5];
        q2 = a * a; q3 = b * b; q4 = c2 * c2; q5 = d * d;
    }
    {
        float v;
        v = wsum(q2); if (l == 0) wred2[wg][0 * 4 + lw] = v;
        v = wsum(q3); if (l == 0) wred2[wg][1 * 4 + lw] = v;
        v = wsum(q4); if (l == 0) wred2[wg][2 * 4 + lw] = v;
        v = wsum(q5); if (l == 0) wred2[wg][3 * 4 + lw] = v;
        GBAR();
        if (lt < 4) {
            float r = 0.f;
            for (int w = 0; w < 4; ++w) r += wred2[wg][lt * 4 + w];
            bres22[wg][lt] = r;
        }
        GBAR();
    }
    const float den2 = fmaxf(sqrtf(bres22[wg][0] + spl[2] * spl[2]), 1e-12f);
    const float den3 = fmaxf(sqrtf(bres22[wg][1] + spl[3] * spl[3]), 1e-12f);
    const float den4 = fmaxf(sqrtf(bres22[wg][2] + spl[4] * spl[4]), 1e-12f);
    const float den5 = fmaxf(sqrtf(bres22[wg][3] + spl[5] * spl[5]), 1e-12f);

    // ---------------- stage-2 pass 2: sl1 / focal / liou over selected rows
    float lsl1 = 0.f, lfl = 0.f, lll = 0.f;
    const int tgt = (p1 > p0) ? 1 : 0;
    if (lt < k) {
        const float* row = feat + (size_t)sel2[wg][lt] * N_FEAT;
        float sacc = 0.f, dd, ad;
        dd = row[2] / den2 - spl[2] / den2; ad = fabsf(dd);
        sacc += (ad < 1.f) ? 0.5f * dd * dd : ad - 0.5f;
        dd = row[3] / den3 - spl[3] / den3; ad = fabsf(dd);
        sacc += (ad < 1.f) ? 0.5f * dd * dd : ad - 0.5f;
        dd = row[4] / den4 - spl[4] / den4; ad = fabsf(dd);
        sacc += (ad < 1.f) ? 0.5f * dd * dd : ad - 0.5f;
        dd = row[5] / den5 - spl[5] / den5; ad = fabsf(dd);
        sacc += (ad < 1.f) ? 0.5f * dd * dd : ad - 0.5f;
        lsl1 = sacc * 0.25f;
        float x0 = row[0], x1 = row[1];
        float mx = fmaxf(x0, x1);
        float lse = mx + logf(expf(x0 - mx) + expf(x1 - mx));
        float logpt = (tgt ? x1 : x0) - lse;
        float pt = expf(logpt);
        lfl = -(1.f - pt) * (1.f - pt) * logpt;
        float L = 0.f;
        #pragma unroll 12
        for (int j = 6; j < 78; ++j) L += fabsf(row[j] - spl[j]);
        lll = 1.f - (2160.f - L) / (2160.f + L + 1e-9f);
    }
    {
        float v;
        v = wsum(lsl1); if (l == 0) wred2[wg][0 * 4 + lw] = v;
        v = wsum(lll);  if (l == 0) wred2[wg][1 * 4 + lw] = v;
        v = wsum(lfl);  if (l == 0) wred2[wg][2 * 4 + lw] = v;
        GBAR();
        if (lt == 0) {
            float ra = 0.f, rb = 0.f, rc = 0.f;
            for (int w = 0; w < 4; ++w) {
                ra += wred2[wg][0 * 4 + w];
                rb += wred2[wg][1 * 4 + w];
                rc += wred2[wg][2 * 4 + w];
            }
            float invk = 1.f / (float)k;
            int task = img * 16 + pair * 2 + wg;
            g_part[task * 3 + 0] = ra * invk;
            g_part[task * 3 + 1] = rb * invk;
            g_part[task * 3 + 2] = rc * invk;
        }
    }

    // ---------------- last-CTA final fold
    __syncthreads();
    if (tid == 0) {
        __threadfence();
        unsigned v = atomicAdd(&g_ctr, 1u);
        sAm = (v == NCTA - 1) ? 1u : 0u;
    }
    __syncthreads();
    if (sAm) {
        if (tid == 0) g_ctr = 0;
        __threadfence();
        float a = 0.f, b = 0.f, c = 0.f;
        for (int i = tid; i < 1024; i += NT) {
            a += g_part[i * 3 + 0];
            b += g_part[i * 3 + 1];
            c += g_part[i * 3 + 2];
        }
        float v;
        v = wsum(a); if (l == 0) wred[0 * 8 + wid] = v;
        v = wsum(b); if (l == 0) wred[1 * 8 + wid] = v;
        v = wsum(c); if (l == 0) wred[2 * 8 + wid] = v;
        __syncthreads();
        if (tid == 0) {
            float sa = 0.f, sb = 0.f, sc = 0.f;
            for (int w = 0; w < 8; ++w) {
                sa += wred[0 * 8 + w]; sb += wred[1 * 8 + w]; sc += wred[2 * 8 + w];
            }
            const float inv = 1.f / 1024.f;
            float sl1l = sa * inv, ll = sb * inv, fl = sc * inv;
            out[0] = (sl1l > 0.f ? 0.5f * sl1l : 0.f)
                   + (ll   > 0.f ? 2.0f * ll   : 0.f)
                   + (fl   > 0.f ? 2.0f * fl   : 0.f);
        }
    }
}

extern "C" void kernel_launch(void* const* d_in, const int* in_sizes, int n_in,
                              void* d_out, int out_size)
{
    const float* output = (const float*)d_in[0];  // [64,1000,78]
    const float* label  = (const float*)d_in[1];  // [64,16,78]
    transpose_kernel<<<NIMG * 32, NT>>>(output);
    lane_kernel<<<NCTA, NT>>>(output, label, (float*)d_out);
}

// round 9
// speedup vs baseline: 4.0049x; 1.0520x over previous
#include <cuda_runtime.h>

#define N_ANCH 1000
#define N_FEAT 78
#define NT     256
#define NCTA   512          // 64 images * 8 CTAs (2 priors each)
#define K_MAX  64
#define FULL   0xffffffffu
#define SPSTR  80
#define NIMG   64

__device__ float    g_featT[(size_t)NIMG * N_FEAT * N_ANCH];  // [img][j][i]
__device__ float    g_part[1024 * 3];
__device__ unsigned g_ctr;
__device__ unsigned g_imgc[NIMG];   // per-image arrival counters (monotonic)

static __device__ __forceinline__ unsigned fkey(float f) {
    unsigned u = __float_as_uint(f);
    return (u & 0x80000000u) ? ~u : (u | 0x80000000u);
}
static __device__ __forceinline__ float wsum(float v) {
    #pragma unroll
    for (int o = 16; o; o >>= 1) v += __shfl_xor_sync(FULL, v, o);
    return v;
}
static __device__ __forceinline__ float wmax(float v) {
    #pragma unroll
    for (int o = 16; o; o >>= 1) v = fmaxf(v, __shfl_xor_sync(FULL, v, o));
    return v;
}
static __device__ __forceinline__ int wscan_incl(int v, int lane) {
    #pragma unroll
    for (int o = 1; o < 32; o <<= 1) {
        int t = __shfl_up_sync(FULL, v, o);
        if (lane >= o) v += t;
    }
    return v;
}

#define GBAR() asm volatile("bar.sync %0, 128;" :: "r"(wg + 1) : "memory")

__global__ __launch_bounds__(NT, 4)
void lane_kernel(const float* __restrict__ output, const float* __restrict__ label,
                 float* __restrict__ out)
{
    __shared__ __align__(16) float pool[4000];   // A0|A1|c0s|c1s; aliased as transpose stage
    __shared__ float spsm[2 * SPSTR];
    __shared__ float wred[12 * 8];
    __shared__ float bres[12];
    __shared__ unsigned sAm;
    __shared__ int   hist2[2][256];
    __shared__ int   iw2[2][4];
    __shared__ int   sel2[2][K_MAX];
    __shared__ int   si22[2][2];
    __shared__ float wred2[2][16];
    __shared__ float bres22[2][4];
    __shared__ int   tbuf[2][64];
    __shared__ int   tcnt[2];

    float* A0  = pool;
    float* A1  = pool + 1000;
    float* c0s = pool + 2000;
    float* c1s = pool + 3000;

    const int tid = threadIdx.x;
    const int wid = tid >> 5;
    const int l   = tid & 31;
    const int bx   = blockIdx.x;
    const int img  = bx >> 3;
    const int pair = bx & 7;
    const float* feat = output + (size_t)img * (N_ANCH * N_FEAT);
    float* ftw = g_featT + (size_t)img * (N_FEAT * N_ANCH);

    // ================ Phase T: transpose own 125-anchor slice =================
    {
        float (*tstage)[33] = (float(*)[33])pool;   // 78*33 = 2574 floats
        const int abase = pair * 125;
        for (int tb = 0; tb < 4; ++tb) {
            const int ibase = abase + tb * 32;
            const int cnt = (abase + 125 - ibase < 32) ? (abase + 125 - ibase) : 32;
            const float* src = feat + (size_t)ibase * N_FEAT;
            for (int idx = tid; idx < cnt * N_FEAT; idx += NT) {
                int r = idx / N_FEAT, c = idx - r * N_FEAT;
                tstage[c][r] = src[idx];
            }
            __syncthreads();
            for (int idx = tid; idx < N_FEAT * 32; idx += NT) {
                int j = idx >> 5, ii = idx & 31;
                if (ii < cnt) ftw[j * N_ANCH + ibase + ii] = tstage[j][ii];
            }
            __syncthreads();
        }
    }
    // signal + wait for the other 7 CTAs of this image (generation counting)
    __threadfence();
    __syncthreads();
    if (tid == 0) {
        unsigned old = atomicAdd(&g_imgc[img], 1u);
        unsigned target = ((old >> 3) + 1u) << 3;
        unsigned v;
        do {
            asm volatile("ld.acquire.gpu.u32 %0, [%1];"
                         : "=r"(v) : "l"(g_imgc + img) : "memory");
            if (v >= target) break;
            __nanosleep(40);
        } while (true);
        __threadfence();
    }
    __syncthreads();

    const float* ft = g_featT + (size_t)img * (N_FEAT * N_ANCH);

    // ================ priors ================
    for (int idx = tid; idx < 2 * N_FEAT; idx += NT) {
        int ll = idx / N_FEAT, j = idx - ll * N_FEAT;
        spsm[ll * SPSTR + j] = label[((size_t)img * 16 + pair * 2 + ll) * N_FEAT + j];
    }
    __syncthreads();

    const bool act = (tid < 250);

    // ---------------- L1 accumulation: thread owns 4 anchors, float4 coalesced
    float La0 = 0.f, La1 = 0.f, La2 = 0.f, La3 = 0.f;
    float Lb0 = 0.f, Lb1 = 0.f, Lb2 = 0.f, Lb3 = 0.f;
    if (act) {
        #pragma unroll 6
        for (int j = 6; j < 78; j += 2) {
            float4 v  = ((const float4*)(ft + j * N_ANCH))[tid];
            float4 v2 = ((const float4*)(ft + (j + 1) * N_ANCH))[tid];
            float2 sa = *(const float2*)&spsm[j];
            float2 sb = *(const float2*)&spsm[SPSTR + j];
            La0 += fabsf(v.x - sa.x); La1 += fabsf(v.y - sa.x);
            La2 += fabsf(v.z - sa.x); La3 += fabsf(v.w - sa.x);
            Lb0 += fabsf(v.x - sb.x); Lb1 += fabsf(v.y - sb.x);
            Lb2 += fabsf(v.z - sb.x); Lb3 += fabsf(v.w - sb.x);
            La0 += fabsf(v2.x - sa.y); La1 += fabsf(v2.y - sa.y);
            La2 += fabsf(v2.z - sa.y); La3 += fabsf(v2.w - sa.y);
            Lb0 += fabsf(v2.x - sb.y); Lb1 += fabsf(v2.y - sb.y);
            Lb2 += fabsf(v2.z - sb.y); Lb3 += fabsf(v2.w - sb.y);
        }
    }

    // ---------------- header cols + per-anchor stage-1 quantities
    float m0 = -3.4e38f, m1 = -3.4e38f;
    float a0 = 0.f, a1 = 0.f, a2 = 0.f, a3 = 0.f;
    float a4 = 0.f, a5 = 0.f, a6 = 0.f, a7 = 0.f;
    if (act) {
        float4 lg0 = ((const float4*)(ft + 0 * N_ANCH))[tid];
        float4 lg1 = ((const float4*)(ft + 1 * N_ANCH))[tid];
        float4 rxv = ((const float4*)(ft + 3 * N_ANCH))[tid];
        float4 ryv = ((const float4*)(ft + 4 * N_ANCH))[tid];
        float4 rtv = ((const float4*)(ft + 5 * N_ANCH))[tid];
        ((float4*)c0s)[tid] = lg0;
        ((float4*)c1s)[tid] = lg1;
        m0 = fmaxf(fmaxf(lg0.x, lg0.y), fmaxf(lg0.z, lg0.w));
        m1 = fmaxf(fmaxf(lg1.x, lg1.y), fmaxf(lg1.z, lg1.w));
        const float p0x = spsm[3], p0y = spsm[4], p0t = spsm[5];
        const float p1x = spsm[SPSTR + 3], p1y = spsm[SPSTR + 4], p1t = spsm[SPSTR + 5];
        float rA[4], rB[4];
        const float rx[4] = {rxv.x, rxv.y, rxv.z, rxv.w};
        const float ry[4] = {ryv.x, ryv.y, ryv.z, ryv.w};
        const float rt[4] = {rtv.x, rtv.y, rtv.z, rtv.w};
        const float Las[4] = {La0, La1, La2, La3};
        const float Lbs[4] = {Lb0, Lb1, Lb2, Lb3};
        #pragma unroll
        for (int a = 0; a < 4; ++a) {
            {
                float dx = rx[a] - p0x, dy = ry[a] - p0y, th = rt[a] - p0t;
                float xy = sqrtf(dx * dx + dy * dy);
                float L = Las[a];
                float dis = L * (1.0f / 72.0f);
                float liou = 1.f - (2160.f - L) / (2160.f + L + 1e-9f);
                rA[a] = dis * xy * th;
                a0 += xy * xy; a1 += th * th; a2 += dis * dis; a3 += liou;
            }
            {
                float dx = rx[a] - p1x, dy = ry[a] - p1y, th = rt[a] - p1t;
                float xy = sqrtf(dx * dx + dy * dy);
                float L = Lbs[a];
                float dis = L * (1.0f / 72.0f);
                float liou = 1.f - (2160.f - L) / (2160.f + L + 1e-9f);
                rB[a] = dis * xy * th;
                a4 += xy * xy; a5 += th * th; a6 += dis * dis; a7 += liou;
            }
        }
        ((float4*)A0)[tid] = make_float4(rA[0], rA[1], rA[2], rA[3]);
        ((float4*)A1)[tid] = make_float4(rB[0], rB[1], rB[2], rB[3]);
    }

    // ---------------- block-reduce 10 quantities
    {
        float v;
        v = wmax(m0); if (l == 0) wred[0 * 8 + wid] = v;
        v = wmax(m1); if (l == 0) wred[1 * 8 + wid] = v;
        v = wsum(a0); if (l == 0) wred[2 * 8 + wid] = v;
        v = wsum(a1); if (l == 0) wred[3 * 8 + wid] = v;
        v = wsum(a2); if (l == 0) wred[4 * 8 + wid] = v;
        v = wsum(a3); if (l == 0) wred[5 * 8 + wid] = v;
        v = wsum(a4); if (l == 0) wred[6 * 8 + wid] = v;
        v = wsum(a5); if (l == 0) wred[7 * 8 + wid] = v;
        v = wsum(a6); if (l == 0) wred[8 * 8 + wid] = v;
        v = wsum(a7); if (l == 0) wred[9 * 8 + wid] = v;
        __syncthreads();
        if (tid < 10) {
            float r = wred[tid * 8];
            if (tid < 2) { for (int w = 1; w < 8; ++w) r = fmaxf(r, wred[tid * 8 + w]); }
            else         { for (int w = 1; w < 8; ++w) r += wred[tid * 8 + w]; }
            bres[tid] = r;
        }
        __syncthreads();
    }
    const float M0 = bres[0], M1 = bres[1];

    // ---------------- softmax sums
    float s0 = 0.f, s1 = 0.f;
    if (act) {
        float4 c = ((const float4*)c0s)[tid];
        s0 = expf(c.x - M0) + expf(c.y - M0) + expf(c.z - M0) + expf(c.w - M0);
        float4 d = ((const float4*)c1s)[tid];
        s1 = expf(d.x - M1) + expf(d.y - M1) + expf(d.z - M1) + expf(d.w - M1);
    }
    {
        float v;
        v = wsum(s0); if (l == 0) wred[0 * 8 + wid] = v;
        v = wsum(s1); if (l == 0) wred[1 * 8 + wid] = v;
        __syncthreads();
        if (tid < 2) {
            float r = 0.f;
            for (int w = 0; w < 8; ++w) r += wred[tid * 8 + w];
            bres[tid] = r;
        }
        __syncthreads();
    }
    const float lse0 = M0 + logf(bres[0]);
    const float lse1 = M1 + logf(bres[1]);

    // ---------------- focal factors (feature-only)
    if (act) {
        float4 c = ((const float4*)c0s)[tid];
        float ls, e;
        ls = c.x - lse0; e = expf(ls); c.x = (1.f - e) * (1.f - e) * ls;
        ls = c.y - lse0; e = expf(ls); c.y = (1.f - e) * (1.f - e) * ls;
        ls = c.z - lse0; e = expf(ls); c.z = (1.f - e) * (1.f - e) * ls;
        ls = c.w - lse0; e = expf(ls); c.w = (1.f - e) * (1.f - e) * ls;
        ((float4*)c0s)[tid] = c;
        float4 d = ((const float4*)c1s)[tid];
        ls = d.x - lse1; e = expf(ls); d.x = (1.f - e) * (1.f - e) * ls;
        ls = d.y - lse1; e = expf(ls); d.y = (1.f - e) * (1.f - e) * ls;
        ls = d.z - lse1; e = expf(ls); d.z = (1.f - e) * (1.f - e) * ls;
        ls = d.w - lse1; e = expf(ls); d.w = (1.f - e) * (1.f - e) * ls;
        ((float4*)c1s)[tid] = d;
    }
    __syncthreads();

    // ================ SPLIT: warps 0-3 -> prior 0, warps 4-7 -> prior 1 ======
    const int wg = wid >> 2;
    const int lt = tid & 127;
    const int lw = (tid >> 5) & 3;

    const float sxy   = bres[2 + wg * 4 + 0];
    const float sth   = bres[2 + wg * 4 + 1];
    const float sdis  = bres[2 + wg * 4 + 2];
    const float sliou = bres[2 + wg * 4 + 3];
    const float Nx  = fmaxf(sqrtf(sxy),  1e-12f);
    const float Nt2 = fmaxf(sqrtf(sth),  1e-12f);
    const float Nd  = fmaxf(sqrtf(sdis), 1e-12f);
    const float invn = 1.f / (Nx * Nt2 * Nd);
    int k = (int)sliou;
    if (k < 1) k = 1;
    if (k > K_MAX) k = K_MAX;
    const float* spl = spsm + wg * SPSTR;
    const float p0 = spl[0], p1 = spl[1];
    float* A = wg ? A1 : A0;

    // cost finalize (128 threads per group, float4 over 250 chunks)
    for (int i4 = lt; i4 < 250; i4 += 128) {
        float4 a = ((const float4*)A)[i4];
        float4 f0 = ((const float4*)c0s)[i4];
        float4 f1 = ((const float4*)c1s)[i4];
        float t;
        t = a.x * invn; a.x = 3.f * t * t + p0 * f0.x + p1 * f1.x;
        t = a.y * invn; a.y = 3.f * t * t + p0 * f0.y + p1 * f1.y;
        t = a.z * invn; a.z = 3.f * t * t + p0 * f0.z + p1 * f1.z;
        t = a.w * invn; a.w = 3.f * t * t + p0 * f0.w + p1 * f1.w;
        ((float4*)A)[i4] = a;
    }
    // zero hist while finalize settles
    hist2[wg][lt] = 0; hist2[wg][lt + 128] = 0;
    GBAR();

    // register-cache this thread's 8 keys (anchors lt, lt+128, ..., lt+896)
    unsigned keys[8];
    #pragma unroll
    for (int q = 0; q < 8; ++q) {
        int i = lt + (q << 7);
        keys[q] = (i < N_ANCH) ? fkey(A[i]) : 0xFFFFFFFFu;
    }

    // ---------------- radix-select k-th smallest (4x8-bit), 2 barriers/pass
    unsigned prefix = 0; int kk = k;
    #pragma unroll
    for (int shift = 24; shift >= 0; shift -= 8) {
        unsigned pmask = (shift == 24) ? 0u : (0xFFFFFFFFu << (shift + 8));
        #pragma unroll
        for (int q = 0; q < 8; ++q) {
            int i = lt + (q << 7);
            if (i < N_ANCH && (keys[q] & pmask) == prefix)
                atomicAdd(&hist2[wg][(keys[q] >> shift) & 255], 1);
        }
        GBAR();
        if (lw == 0) {           // one warp scans 256 bins (8 per lane), re-zeroes
            int b[8]; int s = 0;
            #pragma unroll
            for (int t2 = 0; t2 < 8; ++t2) {
                b[t2] = hist2[wg][l * 8 + t2];
                s += b[t2];
                hist2[wg][l * 8 + t2] = 0;
            }
            int incl = wscan_incl(s, l);
            int excl = incl - s;
            if (kk > excl && kk <= incl) {
                int run = excl, bin = -1, rem = 0;
                #pragma unroll
                for (int t2 = 0; t2 < 8; ++t2) {
                    if (bin < 0 && kk <= run + b[t2]) { bin = l * 8 + t2; rem = kk - run; }
                    run += b[t2];
                }
                si22[wg][0] = bin; si22[wg][1] = rem;
            }
        }
        GBAR();
        prefix |= ((unsigned)si22[wg][0]) << shift;
        kk = si22[wg][1];
    }
    const unsigned T = prefix;
    const int rties = kk;

    // ---------------- tie collection (small buffer, exact semantics)
    if (lt == 0) tcnt[wg] = 0;
    GBAR();
    #pragma unroll
    for (int q = 0; q < 8; ++q) {
        int i = lt + (q << 7);
        if (i < N_ANCH && keys[q] == T) {
            int p = atomicAdd(&tcnt[wg], 1);
            if (p < 64) tbuf[wg][p] = i;
        }
    }
    GBAR();
    const int nt = tcnt[wg];

    auto pick = [&](int q) -> bool {
        int i = lt + (q << 7);
        if (i >= N_ANCH) return false;
        unsigned key = keys[q];
        if (key < T) return true;
        if (key != T) return false;
        int r = 0;
        if (nt <= 64) {
            for (int t2 = 0; t2 < nt; ++t2) r += (tbuf[wg][t2] < i);
        } else {
            for (int j = 0; j < i; ++j) r += (fkey(A[j]) == T);
        }
        return r < rties;
    };

    // ---------------- deterministic compaction
    int cnt = 0;
    #pragma unroll
    for (int q = 0; q < 8; ++q) cnt += pick(q) ? 1 : 0;
    {
        int inc = wscan_incl(cnt, l);
        if (l == 31) iw2[wg][lw] = inc;
        GBAR();
        int off = 0;
        #pragma unroll
        for (int w = 0; w < 4; ++w) if (w < lw) off += iw2[wg][w];
        int o = off + inc - cnt;
        #pragma unroll
        for (int q = 0; q < 8; ++q)
            if (pick(q)) sel2[wg][o++] = lt + (q << 7);
    }
    GBAR();

    // ---------------- stage-2 pass 1: colnorm squares over cols 2..5 (float2)
    float q2 = 0.f, q3 = 0.f, q4 = 0.f, q5 = 0.f;
    if (lt < k) {
        const float2* row2 = (const float2*)(feat + (size_t)sel2[wg][lt] * N_FEAT);
        float2 h1 = row2[1], h2 = row2[2];
        q2 = h1.x * h1.x; q3 = h1.y * h1.y; q4 = h2.x * h2.x; q5 = h2.y * h2.y;
    }
    {
        float v;
        v = wsum(q2); if (l == 0) wred2[wg][0 * 4 + lw] = v;
        v = wsum(q3); if (l == 0) wred2[wg][1 * 4 + lw] = v;
        v = wsum(q4); if (l == 0) wred2[wg][2 * 4 + lw] = v;
        v = wsum(q5); if (l == 0) wred2[wg][3 * 4 + lw] = v;
        GBAR();
        if (lt < 4) {
            float r = 0.f;
            for (int w = 0; w < 4; ++w) r += wred2[wg][lt * 4 + w];
            bres22[wg][lt] = r;
        }
        GBAR();
    }
    const float den2 = fmaxf(sqrtf(bres22[wg][0] + spl[2] * spl[2]), 1e-12f);
    const float den3 = fmaxf(sqrtf(bres22[wg][1] + spl[3] * spl[3]), 1e-12f);
    const float den4 = fmaxf(sqrtf(bres22[wg][2] + spl[4] * spl[4]), 1e-12f);
    const float den5 = fmaxf(sqrtf(bres22[wg][3] + spl[5] * spl[5]), 1e-12f);

    // ---------------- stage-2 pass 2: sl1 / focal / liou (float2 rows)
    float lsl1 = 0.f, lfl = 0.f, lll = 0.f;
    const int tgt = (p1 > p0) ? 1 : 0;
    if (lt < k) {
        const float2* row2 = (const float2*)(feat + (size_t)sel2[wg][lt] * N_FEAT);
        float2 h0 = row2[0], h1 = row2[1], h2 = row2[2];
        float sacc = 0.f, dd, ad;
        dd = h1.x / den2 - spl[2] / den2; ad = fabsf(dd);
        sacc += (ad < 1.f) ? 0.5f * dd * dd : ad - 0.5f;
        dd = h1.y / den3 - spl[3] / den3; ad = fabsf(dd);
        sacc += (ad < 1.f) ? 0.5f * dd * dd : ad - 0.5f;
        dd = h2.x / den4 - spl[4] / den4; ad = fabsf(dd);
        sacc += (ad < 1.f) ? 0.5f * dd * dd : ad - 0.5f;
        dd = h2.y / den5 - spl[5] / den5; ad = fabsf(dd);
        sacc += (ad < 1.f) ? 0.5f * dd * dd : ad - 0.5f;
        lsl1 = sacc * 0.25f;
        float x0 = h0.x, x1 = h0.y;
        float mx = fmaxf(x0, x1);
        float lse = mx + logf(expf(x0 - mx) + expf(x1 - mx));
        float logpt = (tgt ? x1 : x0) - lse;
        float pt = expf(logpt);
        lfl = -(1.f - pt) * (1.f - pt) * logpt;
        float L = 0.f;
        #pragma unroll 9
        for (int jj = 3; jj < 39; ++jj) {
            float2 v = row2[jj];
            float2 s = ((const float2*)spl)[jj];
            L += fabsf(v.x - s.x) + fabsf(v.y - s.y);
        }
        lll = 1.f - (2160.f - L) / (2160.f + L + 1e-9f);
    }
    {
        float v;
        v = wsum(lsl1); if (l == 0) wred2[wg][0 * 4 + lw] = v;
        v = wsum(lll);  if (l == 0) wred2[wg][1 * 4 + lw] = v;
        v = wsum(lfl);  if (l == 0) wred2[wg][2 * 4 + lw] = v;
        GBAR();
        if (lt == 0) {
            float ra = 0.f, rb = 0.f, rc = 0.f;
            for (int w = 0; w < 4; ++w) {
                ra += wred2[wg][0 * 4 + w];
                rb += wred2[wg][1 * 4 + w];
                rc += wred2[wg][2 * 4 + w];
            }
            float invk = 1.f / (float)k;
            int task = img * 16 + pair * 2 + wg;
            g_part[task * 3 + 0] = ra * invk;
            g_part[task * 3 + 1] = rb * invk;
            g_part[task * 3 + 2] = rc * invk;
        }
    }

    // ---------------- last-CTA final fold
    __syncthreads();
    if (tid == 0) {
        __threadfence();
        unsigned v = atomicAdd(&g_ctr, 1u);
        sAm = (v == NCTA - 1) ? 1u : 0u;
    }
    __syncthreads();
    if (sAm) {
        if (tid == 0) g_ctr = 0;
        __threadfence();
        float a = 0.f, b = 0.f, c = 0.f;
        for (int i = tid; i < 1024; i += NT) {
            a += g_part[i * 3 + 0];
            b += g_part[i * 3 + 1];
            c += g_part[i * 3 + 2];
        }
        float v;
        v = wsum(a); if (l == 0) wred[0 * 8 + wid] = v;
        v = wsum(b); if (l == 0) wred[1 * 8 + wid] = v;
        v = wsum(c); if (l == 0) wred[2 * 8 + wid] = v;
        __syncthreads();
        if (tid == 0) {
            float sa = 0.f, sb = 0.f, sc = 0.f;
            for (int w = 0; w < 8; ++w) {
                sa += wred[0 * 8 + w]; sb += wred[1 * 8 + w]; sc += wred[2 * 8 + w];
            }
            const float inv = 1.f / 1024.f;
            float sl1l = sa * inv, ll = sb * inv, fl = sc * inv;
            out[0] = (sl1l > 0.f ? 0.5f * sl1l : 0.f)
                   + (ll   > 0.f ? 2.0f * ll   : 0.f)
                   + (fl   > 0.f ? 2.0f * fl   : 0.f);
        }
    }
}

extern "C" void kernel_launch(void* const* d_in, const int* in_sizes, int n_in,
                              void* d_out, int out_size)
{
    const float* output = (const float*)d_in[0];  // [64,1000,78]
    const float* label  = (const float*)d_in[1];  // [64,16,78]
    lane_kernel<<<NCTA, NT>>>(output, label, (float*)d_out);
}

// round 10
// speedup vs baseline: 4.4255x; 1.1050x over previous
#include <cuda_runtime.h>

#define N_ANCH 1000
#define N_FEAT 78
#define NT     256
#define NCTA   512          // 64 images * 8 CTAs (2 priors each)
#define K_MAX  64
#define FULL   0xffffffffu
#define SPSTR  80
#define NIMG   64

__device__ float    g_featT[(size_t)NIMG * N_FEAT * N_ANCH];  // [img][j][i]
__device__ float    g_part[1024 * 3];
__device__ unsigned g_ctr;
__device__ unsigned g_imgc[NIMG];   // per-image arrival counters (monotonic)

static __device__ __forceinline__ unsigned fkey(float f) {
    unsigned u = __float_as_uint(f);
    return (u & 0x80000000u) ? ~u : (u | 0x80000000u);
}
static __device__ __forceinline__ float wsum(float v) {
    #pragma unroll
    for (int o = 16; o; o >>= 1) v += __shfl_xor_sync(FULL, v, o);
    return v;
}
static __device__ __forceinline__ float wmax(float v) {
    #pragma unroll
    for (int o = 16; o; o >>= 1) v = fmaxf(v, __shfl_xor_sync(FULL, v, o));
    return v;
}
static __device__ __forceinline__ int wscan_incl(int v, int lane) {
    #pragma unroll
    for (int o = 1; o < 32; o <<= 1) {
        int t = __shfl_up_sync(FULL, v, o);
        if (lane >= o) v += t;
    }
    return v;
}

#define GBAR() asm volatile("bar.sync %0, 128;" :: "r"(wg + 1) : "memory")

__global__ __launch_bounds__(NT, 4)
void lane_kernel(const float* __restrict__ output, const float* __restrict__ label,
                 float* __restrict__ out)
{
    __shared__ __align__(16) float pool[4000];   // A0|A1|c0s|c1s; aliased as transpose stage
    __shared__ __align__(16) float liouA[N_ANCH];
    __shared__ __align__(16) float liouB[N_ANCH];
    __shared__ float spsm[2 * SPSTR];
    __shared__ float wred[12 * 8];
    __shared__ float bres[12];
    __shared__ unsigned sAm;
    __shared__ int   hist2[2][256];
    __shared__ int   iw2[2][4];
    __shared__ int   sel2[2][K_MAX];
    __shared__ int   si22[2][2];
    __shared__ float wred2[2][16];
    __shared__ float bres22[2][4];
    __shared__ int   tbuf[2][64];
    __shared__ int   tcnt[2];

    float* A0  = pool;
    float* A1  = pool + 1000;
    float* c0s = pool + 2000;
    float* c1s = pool + 3000;

    const int tid = threadIdx.x;
    const int wid = tid >> 5;
    const int l   = tid & 31;
    const int bx   = blockIdx.x;
    const int img  = bx >> 3;
    const int pair = bx & 7;
    const float* feat = output + (size_t)img * (N_ANCH * N_FEAT);
    float* ftw = g_featT + (size_t)img * (N_FEAT * N_ANCH);

    // ================ Phase T: transpose own 125-anchor slice =================
    {
        float (*tstage)[33] = (float(*)[33])pool;   // 78*33 = 2574 floats
        const int abase = pair * 125;
        for (int tb = 0; tb < 4; ++tb) {
            const int ibase = abase + tb * 32;
            const int cnt = (abase + 125 - ibase < 32) ? (abase + 125 - ibase) : 32;
            // warp wid handles rows wid*4 .. wid*4+3 (coalesced lane reads)
            #pragma unroll
            for (int rr0 = 0; rr0 < 4; ++rr0) {
                const int rr = wid * 4 + rr0;
                if (rr < cnt) {
                    const float* src = feat + (size_t)(ibase + rr) * N_FEAT;
                    float v0 = src[l];
                    float v1 = src[32 + l];
                    tstage[l][rr] = v0;
                    tstage[32 + l][rr] = v1;
                    if (l < 14) tstage[64 + l][rr] = src[64 + l];
                }
            }
            __syncthreads();
            for (int idx = tid; idx < N_FEAT * 32; idx += NT) {
                int j = idx >> 5, ii = idx & 31;
                if (ii < cnt) ftw[j * N_ANCH + ibase + ii] = tstage[j][ii];
            }
            __syncthreads();
        }
    }
    // signal + wait for the other 7 CTAs of this image (generation counting)
    __threadfence();
    __syncthreads();
    if (tid == 0) {
        unsigned old = atomicAdd(&g_imgc[img], 1u);
        unsigned target = ((old >> 3) + 1u) << 3;
        unsigned v;
        do {
            asm volatile("ld.acquire.gpu.u32 %0, [%1];"
                         : "=r"(v) : "l"(g_imgc + img) : "memory");
            if (v >= target) break;
            __nanosleep(40);
        } while (true);
        __threadfence();
    }
    __syncthreads();

    const float* ft = g_featT + (size_t)img * (N_FEAT * N_ANCH);

    // ================ priors ================
    for (int idx = tid; idx < 2 * N_FEAT; idx += NT) {
        int ll = idx / N_FEAT, j = idx - ll * N_FEAT;
        spsm[ll * SPSTR + j] = label[((size_t)img * 16 + pair * 2 + ll) * N_FEAT + j];
    }
    __syncthreads();

    const bool act = (tid < 250);

    // ---------------- L1 accumulation: thread owns 4 anchors, float4 coalesced
    float La0 = 0.f, La1 = 0.f, La2 = 0.f, La3 = 0.f;
    float Lb0 = 0.f, Lb1 = 0.f, Lb2 = 0.f, Lb3 = 0.f;
    if (act) {
        #pragma unroll 6
        for (int j = 6; j < 78; j += 2) {
            float4 v  = ((const float4*)(ft + j * N_ANCH))[tid];
            float4 v2 = ((const float4*)(ft + (j + 1) * N_ANCH))[tid];
            float2 sa = *(const float2*)&spsm[j];
            float2 sb = *(const float2*)&spsm[SPSTR + j];
            La0 += fabsf(v.x - sa.x); La1 += fabsf(v.y - sa.x);
            La2 += fabsf(v.z - sa.x); La3 += fabsf(v.w - sa.x);
            Lb0 += fabsf(v.x - sb.x); Lb1 += fabsf(v.y - sb.x);
            Lb2 += fabsf(v.z - sb.x); Lb3 += fabsf(v.w - sb.x);
            La0 += fabsf(v2.x - sa.y); La1 += fabsf(v2.y - sa.y);
            La2 += fabsf(v2.z - sa.y); La3 += fabsf(v2.w - sa.y);
            Lb0 += fabsf(v2.x - sb.y); Lb1 += fabsf(v2.y - sb.y);
            Lb2 += fabsf(v2.z - sb.y); Lb3 += fabsf(v2.w - sb.y);
        }
    }

    // ---------------- header cols + per-anchor stage-1 quantities
    float m0 = -3.4e38f, m1 = -3.4e38f;
    float a0 = 0.f, a1 = 0.f, a2 = 0.f, a3 = 0.f;
    float a4 = 0.f, a5 = 0.f, a6 = 0.f, a7 = 0.f;
    if (act) {
        float4 lg0 = ((const float4*)(ft + 0 * N_ANCH))[tid];
        float4 lg1 = ((const float4*)(ft + 1 * N_ANCH))[tid];
        float4 rxv = ((const float4*)(ft + 3 * N_ANCH))[tid];
        float4 ryv = ((const float4*)(ft + 4 * N_ANCH))[tid];
        float4 rtv = ((const float4*)(ft + 5 * N_ANCH))[tid];
        ((float4*)c0s)[tid] = lg0;
        ((float4*)c1s)[tid] = lg1;
        m0 = fmaxf(fmaxf(lg0.x, lg0.y), fmaxf(lg0.z, lg0.w));
        m1 = fmaxf(fmaxf(lg1.x, lg1.y), fmaxf(lg1.z, lg1.w));
        const float p0x = spsm[3], p0y = spsm[4], p0t = spsm[5];
        const float p1x = spsm[SPSTR + 3], p1y = spsm[SPSTR + 4], p1t = spsm[SPSTR + 5];
        float rA[4], rB[4], liA[4], liB[4];
        const float rx[4] = {rxv.x, rxv.y, rxv.z, rxv.w};
        const float ry[4] = {ryv.x, ryv.y, ryv.z, ryv.w};
        const float rt[4] = {rtv.x, rtv.y, rtv.z, rtv.w};
        const float Las[4] = {La0, La1, La2, La3};
        const float Lbs[4] = {Lb0, Lb1, Lb2, Lb3};
        #pragma unroll
        for (int a = 0; a < 4; ++a) {
            {
                float dx = rx[a] - p0x, dy = ry[a] - p0y, th = rt[a] - p0t;
                float xy = sqrtf(dx * dx + dy * dy);
                float L = Las[a];
                float dis = L * (1.0f / 72.0f);
                float liou = __fdividef(2.f * L + 1e-9f, 2160.f + L + 1e-9f);
                rA[a] = dis * xy * th; liA[a] = liou;
                a0 += xy * xy; a1 += th * th; a2 += dis * dis; a3 += liou;
            }
            {
                float dx = rx[a] - p1x, dy = ry[a] - p1y, th = rt[a] - p1t;
                float xy = sqrtf(dx * dx + dy * dy);
                float L = Lbs[a];
                float dis = L * (1.0f / 72.0f);
                float liou = __fdividef(2.f * L + 1e-9f, 2160.f + L + 1e-9f);
                rB[a] = dis * xy * th; liB[a] = liou;
                a4 += xy * xy; a5 += th * th; a6 += dis * dis; a7 += liou;
            }
        }
        ((float4*)A0)[tid] = make_float4(rA[0], rA[1], rA[2], rA[3]);
        ((float4*)A1)[tid] = make_float4(rB[0], rB[1], rB[2], rB[3]);
        ((float4*)liouA)[tid] = make_float4(liA[0], liA[1], liA[2], liA[3]);
        ((float4*)liouB)[tid] = make_float4(liB[0], liB[1], liB[2], liB[3]);
    }

    // ---------------- block-reduce 10 quantities
    {
        float v;
        v = wmax(m0); if (l == 0) wred[0 * 8 + wid] = v;
        v = wmax(m1); if (l == 0) wred[1 * 8 + wid] = v;
        v = wsum(a0); if (l == 0) wred[2 * 8 + wid] = v;
        v = wsum(a1); if (l == 0) wred[3 * 8 + wid] = v;
        v = wsum(a2); if (l == 0) wred[4 * 8 + wid] = v;
        v = wsum(a3); if (l == 0) wred[5 * 8 + wid] = v;
        v = wsum(a4); if (l == 0) wred[6 * 8 + wid] = v;
        v = wsum(a5); if (l == 0) wred[7 * 8 + wid] = v;
        v = wsum(a6); if (l == 0) wred[8 * 8 + wid] = v;
        v = wsum(a7); if (l == 0) wred[9 * 8 + wid] = v;
        __syncthreads();
        if (tid < 10) {
            float r = wred[tid * 8];
            if (tid < 2) { for (int w = 1; w < 8; ++w) r = fmaxf(r, wred[tid * 8 + w]); }
            else         { for (int w = 1; w < 8; ++w) r += wred[tid * 8 + w]; }
            bres[tid] = r;
        }
        __syncthreads();
    }
    const float M0 = bres[0], M1 = bres[1];

    // ---------------- softmax sums
    float s0 = 0.f, s1 = 0.f;
    if (act) {
        float4 c = ((const float4*)c0s)[tid];
        s0 = expf(c.x - M0) + expf(c.y - M0) + expf(c.z - M0) + expf(c.w - M0);
        float4 d = ((const float4*)c1s)[tid];
        s1 = expf(d.x - M1) + expf(d.y - M1) + expf(d.z - M1) + expf(d.w - M1);
    }
    {
        float v;
        v = wsum(s0); if (l == 0) wred[0 * 8 + wid] = v;
        v = wsum(s1); if (l == 0) wred[1 * 8 + wid] = v;
        __syncthreads();
        if (tid < 2) {
            float r = 0.f;
            for (int w = 0; w < 8; ++w) r += wred[tid * 8 + w];
            bres[tid] = r;
        }
        __syncthreads();
    }
    const float lse0 = M0 + logf(bres[0]);
    const float lse1 = M1 + logf(bres[1]);

    // ---------------- focal factors (feature-only)
    if (act) {
        float4 c = ((const float4*)c0s)[tid];
        float ls, e;
        ls = c.x - lse0; e = expf(ls); c.x = (1.f - e) * (1.f - e) * ls;
        ls = c.y - lse0; e = expf(ls); c.y = (1.f - e) * (1.f - e) * ls;
        ls = c.z - lse0; e = expf(ls); c.z = (1.f - e) * (1.f - e) * ls;
        ls = c.w - lse0; e = expf(ls); c.w = (1.f - e) * (1.f - e) * ls;
        ((float4*)c0s)[tid] = c;
        float4 d = ((const float4*)c1s)[tid];
        ls = d.x - lse1; e = expf(ls); d.x = (1.f - e) * (1.f - e) * ls;
        ls = d.y - lse1; e = expf(ls); d.y = (1.f - e) * (1.f - e) * ls;
        ls = d.z - lse1; e = expf(ls); d.z = (1.f - e) * (1.f - e) * ls;
        ls = d.w - lse1; e = expf(ls); d.w = (1.f - e) * (1.f - e) * ls;
        ((float4*)c1s)[tid] = d;
    }
    __syncthreads();

    // ================ SPLIT: warps 0-3 -> prior 0, warps 4-7 -> prior 1 ======
    const int wg = wid >> 2;
    const int lt = tid & 127;
    const int lw = (tid >> 5) & 3;

    const float sxy   = bres[2 + wg * 4 + 0];
    const float sth   = bres[2 + wg * 4 + 1];
    const float sdis  = bres[2 + wg * 4 + 2];
    const float sliou = bres[2 + wg * 4 + 3];
    const float Nx  = fmaxf(sqrtf(sxy),  1e-12f);
    const float Nt2 = fmaxf(sqrtf(sth),  1e-12f);
    const float Nd  = fmaxf(sqrtf(sdis), 1e-12f);
    const float invn = 1.f / (Nx * Nt2 * Nd);
    int k = (int)sliou;
    if (k < 1) k = 1;
    if (k > K_MAX) k = K_MAX;
    const float* spl = spsm + wg * SPSTR;
    const float p0 = spl[0], p1 = spl[1];
    float* A = wg ? A1 : A0;
    const float* liou_s = wg ? liouB : liouA;

    // cost finalize (128 threads per group, float4 over 250 chunks)
    for (int i4 = lt; i4 < 250; i4 += 128) {
        float4 a = ((const float4*)A)[i4];
        float4 f0 = ((const float4*)c0s)[i4];
        float4 f1 = ((const float4*)c1s)[i4];
        float t;
        t = a.x * invn; a.x = 3.f * t * t + p0 * f0.x + p1 * f1.x;
        t = a.y * invn; a.y = 3.f * t * t + p0 * f0.y + p1 * f1.y;
        t = a.z * invn; a.z = 3.f * t * t + p0 * f0.z + p1 * f1.z;
        t = a.w * invn; a.w = 3.f * t * t + p0 * f0.w + p1 * f1.w;
        ((float4*)A)[i4] = a;
    }
    // zero hist while finalize settles
    hist2[wg][lt] = 0; hist2[wg][lt + 128] = 0;
    GBAR();

    // register-cache this thread's 8 keys (anchors lt, lt+128, ..., lt+896)
    unsigned keys[8];
    #pragma unroll
    for (int q = 0; q < 8; ++q) {
        int i = lt + (q << 7);
        keys[q] = (i < N_ANCH) ? fkey(A[i]) : 0xFFFFFFFFu;
    }

    // ---------------- radix-select k-th smallest (4x8-bit), 2 barriers/pass
    unsigned prefix = 0; int kk = k;
    #pragma unroll
    for (int shift = 24; shift >= 0; shift -= 8) {
        unsigned pmask = (shift == 24) ? 0u : (0xFFFFFFFFu << (shift + 8));
        #pragma unroll
        for (int q = 0; q < 8; ++q) {
            int i = lt + (q << 7);
            if (i < N_ANCH && (keys[q] & pmask) == prefix)
                atomicAdd(&hist2[wg][(keys[q] >> shift) & 255], 1);
        }
        GBAR();
        if (lw == 0) {           // one warp scans 256 bins (8 per lane), re-zeroes
            int b[8]; int s = 0;
            #pragma unroll
            for (int t2 = 0; t2 < 8; ++t2) {
                b[t2] = hist2[wg][l * 8 + t2];
                s += b[t2];
                hist2[wg][l * 8 + t2] = 0;
            }
            int incl = wscan_incl(s, l);
            int excl = incl - s;
            if (kk > excl && kk <= incl) {
                int run = excl, bin = -1, rem = 0;
                #pragma unroll
                for (int t2 = 0; t2 < 8; ++t2) {
                    if (bin < 0 && kk <= run + b[t2]) { bin = l * 8 + t2; rem = kk - run; }
                    run += b[t2];
                }
                si22[wg][0] = bin; si22[wg][1] = rem;
            }
        }
        GBAR();
        prefix |= ((unsigned)si22[wg][0]) << shift;
        kk = si22[wg][1];
    }
    const unsigned T = prefix;
    const int rties = kk;

    // ---------------- tie collection (small buffer, exact semantics)
    if (lt == 0) tcnt[wg] = 0;
    GBAR();
    #pragma unroll
    for (int q = 0; q < 8; ++q) {
        int i = lt + (q << 7);
        if (i < N_ANCH && keys[q] == T) {
            int p = atomicAdd(&tcnt[wg], 1);
            if (p < 64) tbuf[wg][p] = i;
        }
    }
    GBAR();
    const int nt = tcnt[wg];

    auto pick = [&](int q) -> bool {
        int i = lt + (q << 7);
        if (i >= N_ANCH) return false;
        unsigned key = keys[q];
        if (key < T) return true;
        if (key != T) return false;
        int r = 0;
        if (nt <= 64) {
            for (int t2 = 0; t2 < nt; ++t2) r += (tbuf[wg][t2] < i);
        } else {
            for (int j = 0; j < i; ++j) r += (fkey(A[j]) == T);
        }
        return r < rties;
    };

    // ---------------- deterministic compaction
    int cnt = 0;
    #pragma unroll
    for (int q = 0; q < 8; ++q) cnt += pick(q) ? 1 : 0;
    {
        int inc = wscan_incl(cnt, l);
        if (l == 31) iw2[wg][lw] = inc;
        GBAR();
        int off = 0;
        #pragma unroll
        for (int w = 0; w < 4; ++w) if (w < lw) off += iw2[wg][w];
        int o = off + inc - cnt;
        #pragma unroll
        for (int q = 0; q < 8; ++q)
            if (pick(q)) sel2[wg][o++] = lt + (q << 7);
    }
    GBAR();

    // ---------------- stage-2: single row read (cols 0..5), liou from smem
    float q2 = 0.f, q3 = 0.f, q4 = 0.f, q5 = 0.f;
    float2 h0, h1, h2;
    int si = 0;
    if (lt < k) {
        si = sel2[wg][lt];
        const float2* row2 = (const float2*)(feat + (size_t)si * N_FEAT);
        h0 = row2[0]; h1 = row2[1]; h2 = row2[2];
        q2 = h1.x * h1.x; q3 = h1.y * h1.y; q4 = h2.x * h2.x; q5 = h2.y * h2.y;
    }
    {
        float v;
        v = wsum(q2); if (l == 0) wred2[wg][0 * 4 + lw] = v;
        v = wsum(q3); if (l == 0) wred2[wg][1 * 4 + lw] = v;
        v = wsum(q4); if (l == 0) wred2[wg][2 * 4 + lw] = v;
        v = wsum(q5); if (l == 0) wred2[wg][3 * 4 + lw] = v;
        GBAR();
        if (lt < 4) {
            float r = 0.f;
            for (int w = 0; w < 4; ++w) r += wred2[wg][lt * 4 + w];
            bres22[wg][lt] = r;
        }
        GBAR();
    }
    const float inv2 = __fdividef(1.f, fmaxf(sqrtf(bres22[wg][0] + spl[2] * spl[2]), 1e-12f));
    const float inv3 = __fdividef(1.f, fmaxf(sqrtf(bres22[wg][1] + spl[3] * spl[3]), 1e-12f));
    const float inv4 = __fdividef(1.f, fmaxf(sqrtf(bres22[wg][2] + spl[4] * spl[4]), 1e-12f));
    const float inv5 = __fdividef(1.f, fmaxf(sqrtf(bres22[wg][3] + spl[5] * spl[5]), 1e-12f));

    float lsl1 = 0.f, lfl = 0.f, lll = 0.f;
    const int tgt = (p1 > p0) ? 1 : 0;
    if (lt < k) {
        float sacc = 0.f, dd, ad;
        dd = h1.x * inv2 - spl[2] * inv2; ad = fabsf(dd);
        sacc += (ad < 1.f) ? 0.5f * dd * dd : ad - 0.5f;
        dd = h1.y * inv3 - spl[3] * inv3; ad = fabsf(dd);
        sacc += (ad < 1.f) ? 0.5f * dd * dd : ad - 0.5f;
        dd = h2.x * inv4 - spl[4] * inv4; ad = fabsf(dd);
        sacc += (ad < 1.f) ? 0.5f * dd * dd : ad - 0.5f;
        dd = h2.y * inv5 - spl[5] * inv5; ad = fabsf(dd);
        sacc += (ad < 1.f) ? 0.5f * dd * dd : ad - 0.5f;
        lsl1 = sacc * 0.25f;
        float x0 = h0.x, x1 = h0.y;
        float mx = fmaxf(x0, x1);
        float lse = mx + logf(expf(x0 - mx) + expf(x1 - mx));
        float logpt = (tgt ? x1 : x0) - lse;
        float pt = expf(logpt);
        lfl = -(1.f - pt) * (1.f - pt) * logpt;
        lll = liou_s[si];
    }
    {
        float v;
        v = wsum(lsl1); if (l == 0) wred2[wg][0 * 4 + lw] = v;
        v = wsum(lll);  if (l == 0) wred2[wg][1 * 4 + lw] = v;
        v = wsum(lfl);  if (l == 0) wred2[wg][2 * 4 + lw] = v;
        GBAR();
        if (lt == 0) {
            float ra = 0.f, rb = 0.f, rc = 0.f;
            for (int w = 0; w < 4; ++w) {
                ra += wred2[wg][0 * 4 + w];
                rb += wred2[wg][1 * 4 + w];
                rc += wred2[wg][2 * 4 + w];
            }
            float invk = 1.f / (float)k;
            int task = img * 16 + pair * 2 + wg;
            g_part[task * 3 + 0] = ra * invk;
            g_part[task * 3 + 1] = rb * invk;
            g_part[task * 3 + 2] = rc * invk;
        }
    }

    // ---------------- last-CTA final fold
    __syncthreads();
    if (tid == 0) {
        __threadfence();
        unsigned v = atomicAdd(&g_ctr, 1u);
        sAm = (v == NCTA - 1) ? 1u : 0u;
    }
    __syncthreads();
    if (sAm) {
        if (tid == 0) g_ctr = 0;
        __threadfence();
        float a = 0.f, b = 0.f, c = 0.f;
        for (int i = tid; i < 1024; i += NT) {
            a += g_part[i * 3 + 0];
            b += g_part[i * 3 + 1];
            c += g_part[i * 3 + 2];
        }
        float v;
        v = wsum(a); if (l == 0) wred[0 * 8 + wid] = v;
        v = wsum(b); if (l == 0) wred[1 * 8 + wid] = v;
        v = wsum(c); if (l == 0) wred[2 * 8 + wid] = v;
        __syncthreads();
        if (tid == 0) {
            float sa = 0.f, sb = 0.f, sc = 0.f;
            for (int w = 0; w < 8; ++w) {
                sa += wred[0 * 8 + w]; sb += wred[1 * 8 + w]; sc += wred[2 * 8 + w];
            }
            const float inv = 1.f / 1024.f;
            float sl1l = sa * inv, ll = sb * inv, fl = sc * inv;
            out[0] = (sl1l > 0.f ? 0.5f * sl1l : 0.f)
                   + (ll   > 0.f ? 2.0f * ll   : 0.f)
                   + (fl   > 0.f ? 2.0f * fl   : 0.f);
        }
    }
}

extern "C" void kernel_launch(void* const* d_in, const int* in_sizes, int n_in,
                              void* d_out, int out_size)
{
    const float* output = (const float*)d_in[0];  // [64,1000,78]
    const float* label  = (const float*)d_in[1];  // [64,16,78]
    lane_kernel<<<NCTA, NT>>>(output, label, (float*)d_out);
}

// round 11
// speedup vs baseline: 4.4374x; 1.0027x over previous
#include <cuda_runtime.h>

#define N_ANCH 1000
#define N_FEAT 78
#define NT     256
#define NCTA   512          // 64 images * 8 CTAs; CTA = (slice for stage-1, 2 priors for select)
#define K_MAX  64
#define FULL   0xffffffffu
#define NIMG   64
#define SLICE  125

__device__ float    gA[(size_t)NIMG * 16 * 1000];     // pre-norm product per (img,prior,anchor)
__device__ float    gLiou[(size_t)NIMG * 16 * 1000];
__device__ float    gLogit[(size_t)NIMG * 2 * 1024];  // padded rows for float4
__device__ float    gSums[(size_t)NIMG * 8 * 68];     // per slice: m0,m1, then 16x{sxy,sth,sdis,sliou}
__device__ float    g_part[1024 * 3];
__device__ unsigned g_ctr;
__device__ unsigned g_imgc[NIMG];

static __device__ __forceinline__ unsigned fkey(float f) {
    unsigned u = __float_as_uint(f);
    return (u & 0x80000000u) ? ~u : (u | 0x80000000u);
}
static __device__ __forceinline__ float wsum(float v) {
    #pragma unroll
    for (int o = 16; o; o >>= 1) v += __shfl_xor_sync(FULL, v, o);
    return v;
}
static __device__ __forceinline__ float wmax(float v) {
    #pragma unroll
    for (int o = 16; o; o >>= 1) v = fmaxf(v, __shfl_xor_sync(FULL, v, o));
    return v;
}
static __device__ __forceinline__ int wscan_incl(int v, int lane) {
    #pragma unroll
    for (int o = 1; o < 32; o <<= 1) {
        int t = __shfl_up_sync(FULL, v, o);
        if (lane >= o) v += t;
    }
    return v;
}

#define GBAR() asm volatile("bar.sync %0, 128;" :: "r"(wg + 1) : "memory")

// dynamic smem layout:
//   Phase A: tile[0..9750)  Lbuf[9760..9760+125*17)  spsm[11888..13168)
//   Phase B: f0s[0..1000) f1s[1000..2000) Acst[2000..4000)   (spsm persists)
#define DYN_FLOATS 13168

__global__ __launch_bounds__(NT, 4)
void lane_kernel(const float* __restrict__ output, const float* __restrict__ label,
                 float* __restrict__ out)
{
    extern __shared__ float dyn[];
    float* tile = dyn;
    float* Lbuf = dyn + 9760;     // stride 17 (conflict-free)
    float* spsm = dyn + 11888;    // 16 priors * stride 80

    __shared__ float wred[12 * 8];
    __shared__ float bres[12];
    __shared__ unsigned sAm;
    __shared__ int   hist2[2][256];
    __shared__ int   iw2[2][4];
    __shared__ int   sel2[2][K_MAX];
    __shared__ int   si22[2][2];
    __shared__ float wred2[2][16];
    __shared__ float bres22[2][4];
    __shared__ int   tbuf[2][64];
    __shared__ int   tcnt[2];

    const int tid = threadIdx.x;
    const int wid = tid >> 5;
    const int l   = tid & 31;
    const int bx  = blockIdx.x;
    const int img = bx >> 3;
    const int sl  = bx & 7;
    const float* feat = output + (size_t)img * (N_ANCH * N_FEAT);

    // ---------------- load 16 priors + own contiguous 125-anchor slice
    for (int idx = tid; idx < 16 * N_FEAT; idx += NT) {
        int p = idx / N_FEAT, j = idx - p * N_FEAT;
        spsm[p * 80 + j] = label[((size_t)img * 16 + p) * N_FEAT + j];
    }
    {
        const float* src = feat + (size_t)sl * (SLICE * N_FEAT);
        for (int idx = tid; idx < SLICE * N_FEAT; idx += NT) tile[idx] = src[idx];
    }
    __syncthreads();

    // ---------------- logits out + slice max
    float m0 = -3.4e38f, m1 = -3.4e38f;
    if (tid < SLICE) {
        float v0 = tile[tid * N_FEAT + 0], v1 = tile[tid * N_FEAT + 1];
        gLogit[((size_t)img * 2 + 0) * 1024 + sl * SLICE + tid] = v0;
        gLogit[((size_t)img * 2 + 1) * 1024 + sl * SLICE + tid] = v1;
        m0 = v0; m1 = v1;
    }
    {
        float v;
        v = wmax(m0); if (l == 0) wred[0 * 8 + wid] = v;
        v = wmax(m1); if (l == 0) wred[1 * 8 + wid] = v;
    }

    // ---------------- L1 for all 16 priors: half-anchor per thread
    int a = tid >> 1; if (a > SLICE - 1) a = SLICE - 1;
    const int h = tid & 1;
    const int base = 6 + 36 * h;
    float L[16];
    #pragma unroll
    for (int p = 0; p < 16; ++p) L[p] = 0.f;
    {
        const float* row = tile + a * N_FEAT + base;
        const float* spb = spsm + base;
        #pragma unroll 4
        for (int j = 0; j < 36; ++j) {
            float v = row[j];
            #pragma unroll
            for (int p = 0; p < 16; ++p) L[p] += fabsf(v - spb[p * 80 + j]);
        }
    }
    #pragma unroll
    for (int p = 0; p < 16; ++p) L[p] += __shfl_xor_sync(FULL, L[p], 1);
    if (h == 0 && tid < 2 * SLICE) {
        #pragma unroll
        for (int p = 0; p < 16; ++p) Lbuf[a * 17 + p] = L[p];
    }
    __syncthreads();   // Lbuf + wred(max) visible

    if (tid < 2) {
        float r = wred[tid * 8];
        for (int w = 1; w < 8; ++w) r = fmaxf(r, wred[tid * 8 + w]);
        gSums[((size_t)img * 8 + sl) * 68 + tid] = r;
    }

    // ---------------- per-prior products + slice partial sums (warp w: priors w, w+8)
    {
        #pragma unroll
        for (int pi = 0; pi < 2; ++pi) {
            const int p = wid + 8 * pi;
            const float px = spsm[p * 80 + 3], py = spsm[p * 80 + 4], pt = spsm[p * 80 + 5];
            float sxy = 0.f, sth = 0.f, sdis = 0.f, sliou = 0.f;
            #pragma unroll
            for (int m = 0; m < 4; ++m) {
                int a2 = l + 32 * m;
                if (a2 < SLICE) {
                    float Lv = Lbuf[a2 * 17 + p];
                    float rx = tile[a2 * N_FEAT + 3];
                    float ry = tile[a2 * N_FEAT + 4];
                    float rt = tile[a2 * N_FEAT + 5];
                    float dx = rx - px, dy = ry - py, th = rt - pt;
                    float xy = sqrtf(dx * dx + dy * dy);
                    float dis = Lv * (1.0f / 72.0f);
                    float liou = __fdividef(2.f * Lv + 1e-9f, 2160.f + Lv + 1e-9f);
                    size_t o = ((size_t)img * 16 + p) * 1000 + sl * SLICE + a2;
                    gA[o] = dis * xy * th;
                    gLiou[o] = liou;
                    sxy += xy * xy; sth += th * th; sdis += dis * dis; sliou += liou;
                }
            }
            sxy = wsum(sxy); sth = wsum(sth); sdis = wsum(sdis); sliou = wsum(sliou);
            if (l == 0) {
                float* gs = gSums + ((size_t)img * 8 + sl) * 68 + 2 + p * 4;
                gs[0] = sxy; gs[1] = sth; gs[2] = sdis; gs[3] = sliou;
            }
        }
    }

    // ---------------- per-image generation barrier
    __threadfence();
    __syncthreads();
    if (tid == 0) {
        unsigned old = atomicAdd(&g_imgc[img], 1u);
        unsigned target = ((old >> 3) + 1u) << 3;
        unsigned v;
        do {
            asm volatile("ld.acquire.gpu.u32 %0, [%1];"
                         : "=r"(v) : "l"(g_imgc + img) : "memory");
            if (v >= target) break;
            __nanosleep(40);
        } while (true);
        __threadfence();
    }
    __syncthreads();

    // ================ Phase B: totals, softmax, focal =========================
    float* f0s  = dyn;
    float* f1s  = dyn + 1000;
    float* Acst = dyn + 2000;

    if (tid < 2) {
        float m = -3.4e38f;
        for (int s = 0; s < 8; ++s) m = fmaxf(m, gSums[((size_t)img * 8 + s) * 68 + tid]);
        bres[tid] = m;
    } else if (tid >= 32 && tid < 40) {
        int q = tid - 32;
        int p = 2 * sl + (q >> 2), c = q & 3;
        float t = 0.f;
        for (int s = 0; s < 8; ++s) t += gSums[((size_t)img * 8 + s) * 68 + 2 + p * 4 + c];
        bres[2 + q] = t;
    }
    __syncthreads();
    const float M0 = bres[0], M1 = bres[1];

    const float* gl0 = gLogit + ((size_t)img * 2 + 0) * 1024;
    const float* gl1 = gLogit + ((size_t)img * 2 + 1) * 1024;
    const bool act = (tid < 250);
    float s0 = 0.f, s1 = 0.f;
    if (act) {
        float4 c = ((const float4*)gl0)[tid];
        ((float4*)f0s)[tid] = c;
        s0 = expf(c.x - M0) + expf(c.y - M0) + expf(c.z - M0) + expf(c.w - M0);
        float4 d = ((const float4*)gl1)[tid];
        ((float4*)f1s)[tid] = d;
        s1 = expf(d.x - M1) + expf(d.y - M1) + expf(d.z - M1) + expf(d.w - M1);
    }
    {
        float v;
        v = wsum(s0); if (l == 0) wred[0 * 8 + wid] = v;
        v = wsum(s1); if (l == 0) wred[1 * 8 + wid] = v;
        __syncthreads();
        if (tid < 2) {
            float r = 0.f;
            for (int w = 0; w < 8; ++w) r += wred[tid * 8 + w];
            bres[10 + tid] = r;
        }
        __syncthreads();
    }
    const float lse0 = M0 + logf(bres[10]);
    const float lse1 = M1 + logf(bres[11]);

    if (act) {
        float4 c = ((const float4*)f0s)[tid];
        float ls, e;
        ls = c.x - lse0; e = expf(ls); c.x = (1.f - e) * (1.f - e) * ls;
        ls = c.y - lse0; e = expf(ls); c.y = (1.f - e) * (1.f - e) * ls;
        ls = c.z - lse0; e = expf(ls); c.z = (1.f - e) * (1.f - e) * ls;
        ls = c.w - lse0; e = expf(ls); c.w = (1.f - e) * (1.f - e) * ls;
        ((float4*)f0s)[tid] = c;
        float4 d = ((const float4*)f1s)[tid];
        ls = d.x - lse1; e = expf(ls); d.x = (1.f - e) * (1.f - e) * ls;
        ls = d.y - lse1; e = expf(ls); d.y = (1.f - e) * (1.f - e) * ls;
        ls = d.z - lse1; e = expf(ls); d.z = (1.f - e) * (1.f - e) * ls;
        ls = d.w - lse1; e = expf(ls); d.w = (1.f - e) * (1.f - e) * ls;
        ((float4*)f1s)[tid] = d;
    }
    __syncthreads();

    // ================ SPLIT: group wg handles prior 2*sl+wg ===================
    const int wg = wid >> 2;
    const int lt = tid & 127;
    const int lw = (tid >> 5) & 3;
    const int prior = 2 * sl + wg;

    const float sxy   = bres[2 + wg * 4 + 0];
    const float sth   = bres[2 + wg * 4 + 1];
    const float sdis  = bres[2 + wg * 4 + 2];
    const float sliou = bres[2 + wg * 4 + 3];
    const float Nx  = fmaxf(sqrtf(sxy),  1e-12f);
    const float Nt2 = fmaxf(sqrtf(sth),  1e-12f);
    const float Nd  = fmaxf(sqrtf(sdis), 1e-12f);
    const float invn = 1.f / (Nx * Nt2 * Nd);
    int k = (int)sliou;
    if (k < 1) k = 1;
    if (k > K_MAX) k = K_MAX;
    const float* spl = spsm + prior * 80;
    const float pr0 = spl[0], pr1 = spl[1];
    const float* gAp = gA    + ((size_t)img * 16 + prior) * 1000;
    const float* gLp = gLiou + ((size_t)img * 16 + prior) * 1000;
    float* Ac = Acst + wg * 1000;

    hist2[wg][lt] = 0; hist2[wg][lt + 128] = 0;
    unsigned keys[8];
    #pragma unroll
    for (int q = 0; q < 8; ++q) {
        int i = lt + (q << 7);
        if (i < N_ANCH) {
            float av = gAp[i];
            float t = av * invn;
            float cost = 3.f * t * t + pr0 * f0s[i] + pr1 * f1s[i];
            Ac[i] = cost;
            keys[q] = fkey(cost);
        } else keys[q] = 0xFFFFFFFFu;
    }
    GBAR();

    // ---------------- radix-select k-th smallest (4x8-bit), 2 barriers/pass
    unsigned prefix = 0; int kk = k;
    #pragma unroll
    for (int shift = 24; shift >= 0; shift -= 8) {
        unsigned pmask = (shift == 24) ? 0u : (0xFFFFFFFFu << (shift + 8));
        #pragma unroll
        for (int q = 0; q < 8; ++q) {
            int i = lt + (q << 7);
            if (i < N_ANCH && (keys[q] & pmask) == prefix)
                atomicAdd(&hist2[wg][(keys[q] >> shift) & 255], 1);
        }
        GBAR();
        if (lw == 0) {
            int b[8]; int s = 0;
            #pragma unroll
            for (int t2 = 0; t2 < 8; ++t2) {
                b[t2] = hist2[wg][l * 8 + t2];
                s += b[t2];
                hist2[wg][l * 8 + t2] = 0;
            }
            int incl = wscan_incl(s, l);
            int excl = incl - s;
            if (kk > excl && kk <= incl) {
                int run = excl, bin = -1, rem = 0;
                #pragma unroll
                for (int t2 = 0; t2 < 8; ++t2) {
                    if (bin < 0 && kk <= run + b[t2]) { bin = l * 8 + t2; rem = kk - run; }
                    run += b[t2];
                }
                si22[wg][0] = bin; si22[wg][1] = rem;
            }
        }
        GBAR();
        prefix |= ((unsigned)si22[wg][0]) << shift;
        kk = si22[wg][1];
    }
    const unsigned T = prefix;
    const int rties = kk;

    // ---------------- tie collection (exact semantics)
    if (lt == 0) tcnt[wg] = 0;
    GBAR();
    #pragma unroll
    for (int q = 0; q < 8; ++q) {
        int i = lt + (q << 7);
        if (i < N_ANCH && keys[q] == T) {
            int p = atomicAdd(&tcnt[wg], 1);
            if (p < 64) tbuf[wg][p] = i;
        }
    }
    GBAR();
    const int nt = tcnt[wg];

    auto pick = [&](int q) -> bool {
        int i = lt + (q << 7);
        if (i >= N_ANCH) return false;
        unsigned key = keys[q];
        if (key < T) return true;
        if (key != T) return false;
        int r = 0;
        if (nt <= 64) {
            for (int t2 = 0; t2 < nt; ++t2) r += (tbuf[wg][t2] < i);
        } else {
            for (int j = 0; j < i; ++j) r += (fkey(Ac[j]) == T);
        }
        return r < rties;
    };

    // ---------------- deterministic compaction
    int cnt = 0;
    #pragma unroll
    for (int q = 0; q < 8; ++q) cnt += pick(q) ? 1 : 0;
    {
        int inc = wscan_incl(cnt, l);
        if (l == 31) iw2[wg][lw] = inc;
        GBAR();
        int off = 0;
        #pragma unroll
        for (int w = 0; w < 4; ++w) if (w < lw) off += iw2[wg][w];
        int o = off + inc - cnt;
        #pragma unroll
        for (int q = 0; q < 8; ++q)
            if (pick(q)) sel2[wg][o++] = lt + (q << 7);
    }
    GBAR();

    // ---------------- stage-2: one scattered row read (cols 0..5) + liou gather
    float q2 = 0.f, q3 = 0.f, q4 = 0.f, q5 = 0.f;
    float2 h0, h1, h2;
    int si = 0;
    if (lt < k) {
        si = sel2[wg][lt];
        const float2* row2 = (const float2*)(feat + (size_t)si * N_FEAT);
        h0 = row2[0]; h1 = row2[1]; h2 = row2[2];
        q2 = h1.x * h1.x; q3 = h1.y * h1.y; q4 = h2.x * h2.x; q5 = h2.y * h2.y;
    }
    {
        float v;
        v = wsum(q2); if (l == 0) wred2[wg][0 * 4 + lw] = v;
        v = wsum(q3); if (l == 0) wred2[wg][1 * 4 + lw] = v;
        v = wsum(q4); if (l == 0) wred2[wg][2 * 4 + lw] = v;
        v = wsum(q5); if (l == 0) wred2[wg][3 * 4 + lw] = v;
        GBAR();
        if (lt < 4) {
            float r = 0.f;
            for (int w = 0; w < 4; ++w) r += wred2[wg][lt * 4 + w];
            bres22[wg][lt] = r;
        }
        GBAR();
    }
    const float inv2 = __fdividef(1.f, fmaxf(sqrtf(bres22[wg][0] + spl[2] * spl[2]), 1e-12f));
    const float inv3 = __fdividef(1.f, fmaxf(sqrtf(bres22[wg][1] + spl[3] * spl[3]), 1e-12f));
    const float inv4 = __fdividef(1.f, fmaxf(sqrtf(bres22[wg][2] + spl[4] * spl[4]), 1e-12f));
    const float inv5 = __fdividef(1.f, fmaxf(sqrtf(bres22[wg][3] + spl[5] * spl[5]), 1e-12f));

    float lsl1 = 0.f, lfl = 0.f, lll = 0.f;
    const int tgt = (pr1 > pr0) ? 1 : 0;
    if (lt < k) {
        float sacc = 0.f, dd, ad;
        dd = h1.x * inv2 - spl[2] * inv2; ad = fabsf(dd);
        sacc += (ad < 1.f) ? 0.5f * dd * dd : ad - 0.5f;
        dd = h1.y * inv3 - spl[3] * inv3; ad = fabsf(dd);
        sacc += (ad < 1.f) ? 0.5f * dd * dd : ad - 0.5f;
        dd = h2.x * inv4 - spl[4] * inv4; ad = fabsf(dd);
        sacc += (ad < 1.f) ? 0.5f * dd * dd : ad - 0.5f;
        dd = h2.y * inv5 - spl[5] * inv5; ad = fabsf(dd);
        sacc += (ad < 1.f) ? 0.5f * dd * dd : ad - 0.5f;
        lsl1 = sacc * 0.25f;
        float x0 = h0.x, x1 = h0.y;
        float mx = fmaxf(x0, x1);
        float lse = mx + logf(expf(x0 - mx) + expf(x1 - mx));
        float logpt = (tgt ? x1 : x0) - lse;
        float pt = expf(logpt);
        lfl = -(1.f - pt) * (1.f - pt) * logpt;
        lll = gLp[si];
    }
    {
        float v;
        v = wsum(lsl1); if (l == 0) wred2[wg][0 * 4 + lw] = v;
        v = wsum(lll);  if (l == 0) wred2[wg][1 * 4 + lw] = v;
        v = wsum(lfl);  if (l == 0) wred2[wg][2 * 4 + lw] = v;
        GBAR();
        if (lt == 0) {
            float ra = 0.f, rb = 0.f, rc = 0.f;
            for (int w = 0; w < 4; ++w) {
                ra += wred2[wg][0 * 4 + w];
                rb += wred2[wg][1 * 4 + w];
                rc += wred2[wg][2 * 4 + w];
            }
            float invk = 1.f / (float)k;
            int task = img * 16 + prior;
            g_part[task * 3 + 0] = ra * invk;
            g_part[task * 3 + 1] = rb * invk;
            g_part[task * 3 + 2] = rc * invk;
        }
    }

    // ---------------- last-CTA final fold
    __syncthreads();
    if (tid == 0) {
        __threadfence();
        unsigned v = atomicAdd(&g_ctr, 1u);
        sAm = (v == NCTA - 1) ? 1u : 0u;
    }
    __syncthreads();
    if (sAm) {
        if (tid == 0) g_ctr = 0;
        __threadfence();
        float a2 = 0.f, b2 = 0.f, c2 = 0.f;
        for (int i = tid; i < 1024; i += NT) {
            a2 += g_part[i * 3 + 0];
            b2 += g_part[i * 3 + 1];
            c2 += g_part[i * 3 + 2];
        }
        float v;
        v = wsum(a2); if (l == 0) wred[0 * 8 + wid] = v;
        v = wsum(b2); if (l == 0) wred[1 * 8 + wid] = v;
        v = wsum(c2); if (l == 0) wred[2 * 8 + wid] = v;
        __syncthreads();
        if (tid == 0) {
            float sa = 0.f, sb = 0.f, sc = 0.f;
            for (int w = 0; w < 8; ++w) {
                sa += wred[0 * 8 + w]; sb += wred[1 * 8 + w]; sc += wred[2 * 8 + w];
            }
            const float inv = 1.f / 1024.f;
            float sl1l = sa * inv, ll = sb * inv, fl = sc * inv;
            out[0] = (sl1l > 0.f ? 0.5f * sl1l : 0.f)
                   + (ll   > 0.f ? 2.0f * ll   : 0.f)
                   + (fl   > 0.f ? 2.0f * fl   : 0.f);
        }
    }
}

extern "C" void kernel_launch(void* const* d_in, const int* in_sizes, int n_in,
                              void* d_out, int out_size)
{
    const float* output = (const float*)d_in[0];  // [64,1000,78]
    const float* label  = (const float*)d_in[1];  // [64,16,78]
    static bool attr_done = false;
    if (!attr_done) {
        cudaFuncSetAttribute(lane_kernel,
                             cudaFuncAttributeMaxDynamicSharedMemorySize,
                             DYN_FLOATS * sizeof(float));
        attr_done = true;
    }
    lane_kernel<<<NCTA, NT, DYN_FLOATS * sizeof(float)>>>(output, label, (float*)d_out);
}